// round 15
// baseline (speedup 1.0000x reference)
#include <cuda_runtime.h>
#include <cuda_bf16.h>
#include <math.h>
#include <stdint.h>

#define NB 64
#define NT 32
#define NR 49
#define FLOC 1024
#define NQ 512
#define NE 256
#define NH 512
#define NV 10000
#define G4 2048   // 4*HID
#define XD 1024   // [o(512), h(512)]
#define UD 1536   // [a(1024), h(512)]
#define NBLK 128  // persistent kernel grid (co-resident)

typedef unsigned long long ull;

// loop smem layout (bytes): [0, 33280) scratch/staging union, then resident
// tiles: A_o (40960), A_h (40960), E (30720)
#define SCRATCH_B 33280
#define WAO_B     40960   // 4kb x 2(hi/lo) x 64row x 40 x 2B
#define WAH_B     40960
#define WE_B      30720   // 3kb x 2 x 64row x 40 x 2B
#define SMEMB     (SCRATCH_B + WAO_B + WAH_B + WE_B)

// ---------------- scratch (device globals; no allocation allowed) ----------
__device__ __nv_bfloat16 g_Wrechi[G4 * XD];   // recurrent weight hi/lo
__device__ __nv_bfloat16 g_Wreclo[G4 * XD];
__device__ __nv_bfloat16 g_Wuhi[NH * UD];     // W_u hi/lo
__device__ __nv_bfloat16 g_Wulo[NH * UD];
__device__ __nv_bfloat16 g_Wvhi[NV * NH];     // W_vocab hi/lo
__device__ __nv_bfloat16 g_Wvlo[NV * NH];
__device__ float g_yseq[NT * NB * NE];        // teacher-forced input embeddings
__device__ float g_gatesy[NT * NB * G4];      // y @ W_ihy^T + b_ih + b_hh
__device__ float g_attnproj[NB * NR * NH];    // local @ W_attn^T  [b][r][h]
__device__ __nv_bfloat16 g_xhi[NB * XD];      // [o,h] activations hi/lo
__device__ __nv_bfloat16 g_xlo[NB * XD];
__device__ __nv_bfloat16 g_uhi[NB * UD];      // [a,h] activations hi/lo
__device__ __nv_bfloat16 g_ulo[NB * UD];
__device__ __nv_bfloat16 g_ohi[NT * NB * NH]; // all o_t hi/lo (vocab A)
__device__ __nv_bfloat16 g_olo[NT * NB * NH];
__device__ float g_P[12 * NB * G4];           // A-stage k-split partials
__device__ float g_Q[16 * NB * NH];           // E-stage k-split partials
__device__ volatile unsigned int g_arr[NBLK];

// ---------------- helpers ----------------------------------------------------
__device__ __forceinline__ ull pack2(float a, float b) {
    ull r; asm("mov.b64 %0, {%1, %2};" : "=l"(r) : "f"(a), "f"(b)); return r;
}
__device__ __forceinline__ float2 unpack2(ull v) {
    float2 r; asm("mov.b64 {%0, %1}, %2;" : "=f"(r.x), "=f"(r.y) : "l"(v)); return r;
}
__device__ __forceinline__ void ffma2(ull& acc, ull a, ull b) {
    asm("fma.rn.f32x2 %0, %1, %2, %0;" : "+l"(acc) : "l"(a), "l"(b));
}
__device__ __forceinline__ void split2(float v, __nv_bfloat16& hi, __nv_bfloat16& lo) {
    hi = __float2bfloat16(v);
    lo = __float2bfloat16(v - __bfloat162float(hi));
}
__device__ __forceinline__ uint32_t pbf2(__nv_bfloat16 a, __nv_bfloat16 b) {
    __nv_bfloat162 t = __halves2bfloat162(a, b);
    return *(uint32_t*)&t;
}

#define MMA_BF16(c, a, b) \
    asm volatile("mma.sync.aligned.m16n8k16.row.col.f32.bf16.bf16.f32 " \
        "{%0,%1,%2,%3}, {%4,%5,%6,%7}, {%8,%9}, {%0,%1,%2,%3};" \
        : "+f"((c)[0]), "+f"((c)[1]), "+f"((c)[2]), "+f"((c)[3]) \
        : "r"((a)[0]), "r"((a)[1]), "r"((a)[2]), "r"((a)[3]), \
          "r"((b)[0]), "r"((b)[1]))

// ---------------- distributed grid barrier (single L2 round-trip) -----------
// Every block: publish own epoch flag, then threads 0..127 each poll one
// block's flag. No coordinator, no release variable.
__device__ __forceinline__ void gbar(unsigned int e) {
    __syncthreads();
    if (threadIdx.x == 0) {
        __threadfence();
        g_arr[blockIdx.x] = e;
    }
    if (threadIdx.x < NBLK) {
        while (g_arr[threadIdx.x] < e) { }
    }
    __threadfence();
    __syncthreads();
}

// ---------------- fp32 GEMM core (prologue only): 64(m) x 64(n) -------------
__device__ __forceinline__ void gemm_core64(
    const float* __restrict__ X, int ldx,
    const float* __restrict__ W, int ldw,
    int n0, int kbase, int kSteps64,
    float* smem, int tid, ull acc[4][4])
{
    float* xs = smem;
    float* ws = smem + 64 * 65;
    int tx = tid & 15, ty = tid >> 4;
    for (int kb = 0; kb < kSteps64; kb++) {
        int kpos = kbase + kb * 64;
        #pragma unroll
        for (int it = 0; it < 4; it++) {
            int idx = it * 256 + tid;
            int row = idx >> 4, kq = (idx & 15) << 2;
            float4 v = __ldcg((const float4*)(X + row * ldx + kpos + kq));
            float* d = &xs[row * 65 + kq];
            d[0] = v.x; d[1] = v.y; d[2] = v.z; d[3] = v.w;
            float4 w = *(const float4*)(W + (size_t)(n0 + row) * ldw + kpos + kq);
            float* e = &ws[row * 65 + kq];
            e[0] = w.x; e[1] = w.y; e[2] = w.z; e[3] = w.w;
        }
        __syncthreads();
        #pragma unroll 8
        for (int k = 0; k < 64; k++) {
            ull xd[4];
            #pragma unroll
            for (int i = 0; i < 4; i++) {
                float x = xs[(ty * 4 + i) * 65 + k];
                xd[i] = pack2(x, x);
            }
            float a0 = ws[(tx * 4 + 0) * 65 + k];
            float a1 = ws[(tx * 4 + 1) * 65 + k];
            float a2 = ws[(tx * 4 + 2) * 65 + k];
            float a3 = ws[(tx * 4 + 3) * 65 + k];
            ull wA0 = pack2(a0, a1), wA1 = pack2(a2, a3);
            #pragma unroll
            for (int i = 0; i < 4; i++) {
                ffma2(acc[i][0], xd[i], wA0);
                ffma2(acc[i][1], xd[i], wA1);
            }
        }
        __syncthreads();
    }
}

__device__ __forceinline__ void store_part64(ull acc[4][4], int kc, int n0, int N, int tid)
{
    int tx = tid & 15, ty = tid >> 4;
    #pragma unroll
    for (int i = 0; i < 4; i++) {
        int m = ty * 4 + i;
        float* dst = &g_P[((kc << 6) + m) * N + n0];
        #pragma unroll
        for (int jj = 0; jj < 2; jj++)
            *(float2*)(dst + tx * 4 + jj * 2) = unpack2(acc[i][jj]);
    }
}

// ---------------- resident-weight bf16 mma core -----------------------------
template<int BN, int KSTEPS>
__device__ __forceinline__ void mma_res(
    const __nv_bfloat16* __restrict__ Ahi, const __nv_bfloat16* __restrict__ Alo,
    int lda, int kbase,
    const __nv_bfloat16* __restrict__ wRes,
    __nv_bfloat16* sA, int tid, float (&acc)[2][BN / 32][4])
{
    constexpr int NG = BN / 32;
    constexpr int ABUF = 2 * 64 * 40;
    const int lane = tid & 31, wid = tid >> 5;
    const int mw = wid >> 2, nw = wid & 3;
    const int gid = lane >> 2, cid = lane & 3;

    const int pidx0 = tid, pidx1 = 256 + tid;
    const int arr0 = pidx0 >> 8, row0 = (pidx0 & 255) >> 2, c80 = ((pidx0 & 255) & 3) * 8;
    const int arr1 = pidx1 >> 8, row1 = (pidx1 & 255) >> 2, c81 = ((pidx1 & 255) & 3) * 8;
    const __nv_bfloat16* a0base = (arr0 ? Alo : Ahi) + (size_t)row0 * lda + kbase + c80;
    const __nv_bfloat16* a1base = (arr1 ? Alo : Ahi) + (size_t)row1 * lda + kbase + c81;
    const int s0off = (arr0 * 64 + row0) * 40 + c80;
    const int s1off = (arr1 * 64 + row1) * 40 + c81;

    *(uint4*)(&sA[s0off]) = __ldcg((const uint4*)a0base);
    *(uint4*)(&sA[s1off]) = __ldcg((const uint4*)a1base);
    __syncthreads();

    for (int kb = 0; kb < KSTEPS; kb++) {
        uint4 pre0, pre1;
        bool haveNext = (kb + 1 < KSTEPS);
        if (haveNext) {
            pre0 = __ldcg((const uint4*)(a0base + (kb + 1) * 32));
            pre1 = __ldcg((const uint4*)(a1base + (kb + 1) * 32));
        }
        const __nv_bfloat16* sAc = sA + (kb & 1) * ABUF;
        const __nv_bfloat16* sB = wRes + (size_t)kb * (2 * BN * 40);
        #pragma unroll
        for (int kh = 0; kh < 2; kh++) {
            int k0 = kh * 16 + 2 * cid;
            uint32_t a[2][4], bh[NG][2], bl[NG][2];
            #pragma unroll
            for (int f = 0; f < 2; f++) {
                const __nv_bfloat16* ap = &sAc[(mw * 32 + f * 16 + gid) * 40 + k0];
                a[f][0] = *(const uint32_t*)ap;
                a[f][1] = *(const uint32_t*)(ap + 8 * 40);
                a[f][2] = *(const uint32_t*)(ap + 8);
                a[f][3] = *(const uint32_t*)(ap + 8 * 40 + 8);
            }
            #pragma unroll
            for (int g = 0; g < NG; g++) {
                const __nv_bfloat16* bp = &sB[(nw * (BN / 4) + g * 8 + gid) * 40 + k0];
                bh[g][0] = *(const uint32_t*)bp;
                bh[g][1] = *(const uint32_t*)(bp + 8);
                const __nv_bfloat16* bq = bp + (size_t)BN * 40;
                bl[g][0] = *(const uint32_t*)bq;
                bl[g][1] = *(const uint32_t*)(bq + 8);
            }
            #pragma unroll
            for (int f = 0; f < 2; f++)
                #pragma unroll
                for (int g = 0; g < NG; g++) {
                    MMA_BF16(acc[f][g], a[f], bh[g]);
                    MMA_BF16(acc[f][g], a[f], bl[g]);
                }
            #pragma unroll
            for (int f = 0; f < 2; f++) {
                const __nv_bfloat16* ap = &sAc[(64 + mw * 32 + f * 16 + gid) * 40 + k0];
                a[f][0] = *(const uint32_t*)ap;
                a[f][1] = *(const uint32_t*)(ap + 8 * 40);
                a[f][2] = *(const uint32_t*)(ap + 8);
                a[f][3] = *(const uint32_t*)(ap + 8 * 40 + 8);
            }
            #pragma unroll
            for (int f = 0; f < 2; f++)
                #pragma unroll
                for (int g = 0; g < NG; g++)
                    MMA_BF16(acc[f][g], a[f], bh[g]);
        }
        if (haveNext) {
            __nv_bfloat16* sAn = sA + ((kb + 1) & 1) * ABUF;
            *(uint4*)(&sAn[s0off]) = pre0;
            *(uint4*)(&sAn[s1off]) = pre1;
        }
        __syncthreads();
    }
}

template<int NG>
__device__ __forceinline__ void mma_store_t(float (&acc)[2][NG][4], float* buf,
                                            int slot, int n0, int N, int tid)
{
    const int lane = tid & 31, wid = tid >> 5;
    const int mw = wid >> 2, nw = wid & 3;
    const int gid = lane >> 2, cid = lane & 3;
    #pragma unroll
    for (int f = 0; f < 2; f++)
        #pragma unroll
        for (int half = 0; half < 2; half++) {
            int m = mw * 32 + f * 16 + gid + half * 8;
            float* dst = buf + ((slot << 6) + m) * N + n0 + nw * 8 * NG + 2 * cid;
            #pragma unroll
            for (int g = 0; g < NG; g++)
                *(float2*)(dst + g * 8) =
                    make_float2(acc[f][g][half * 2], acc[f][g][half * 2 + 1]);
        }
}

template<int NG>
__device__ __forceinline__ void zacc(float (&acc)[2][NG][4]) {
    #pragma unroll
    for (int f = 0; f < 2; f++)
        #pragma unroll
        for (int g = 0; g < NG; g++)
            #pragma unroll
            for (int e = 0; e < 4; e++) acc[f][g][e] = 0.f;
}

// ---------------- one-time prep: weight splits + embed gather ---------------
__global__ void prep_kernel(const float* __restrict__ W_ih,
                            const float* __restrict__ W_hh,
                            const float* __restrict__ W_u,
                            const float* __restrict__ emb,
                            const int*   __restrict__ answers,
                            const float* __restrict__ W_vocab)
{
    int stride = gridDim.x * blockDim.x;
    int tid0 = blockIdx.x * blockDim.x + threadIdx.x;
    for (int i = tid0; i < G4 * XD; i += stride) {
        int n = i >> 10, k = i & 1023;
        float w = (k < NH) ? W_ih[n * 768 + 256 + k] : W_hh[n * NH + (k - NH)];
        split2(w, g_Wrechi[i], g_Wreclo[i]);
    }
    for (int i = tid0; i < NH * UD; i += stride)
        split2(W_u[i], g_Wuhi[i], g_Wulo[i]);
    for (int i = tid0; i < NV * NH; i += stride)
        split2(W_vocab[i], g_Wvhi[i], g_Wvlo[i]);
    for (int i = tid0; i < NT * NB * NE; i += stride) {
        int m = i >> 8, e = i & 255;
        int t = m >> 6, b = m & 63;
        int tok = (t == 0) ? 1 : answers[b * NT + (t - 1)];
        g_yseq[i] = emb[tok * NE + e];
    }
}

// ---------------- persistent recurrent-loop kernel -------------------------
__global__ void __launch_bounds__(256, 1)
loop_kernel(const float* __restrict__ local,
            const float* __restrict__ b_u,
            const float* __restrict__ q,
            const float* __restrict__ W_h,
            const float* __restrict__ W_c,
            const float* __restrict__ globalf,
            const float* __restrict__ W_g2o,
            const float* __restrict__ b_g2o)
{
    extern __shared__ float smem[];
    __nv_bfloat16* smb = (__nv_bfloat16*)smem;              // staging (bf16 view)
    __nv_bfloat16* wAo = smb + SCRATCH_B / 2;               // resident A o-tile
    __nv_bfloat16* wAh = smb + (SCRATCH_B + WAO_B) / 2;     // resident A h-tile
    __nv_bfloat16* wE  = smb + (SCRATCH_B + WAO_B + WAH_B) / 2;  // resident E tile
    const int bid = blockIdx.x;
    const int tid = threadIdx.x;
    const int ntA = bid & 31, kcA = bid >> 5;     // A tiles: 64n x 128k
    const int ntE = bid & 7,  kcE = bid >> 3;     // E tile : 64n x 96k
    unsigned int ep = g_arr[bid];                 // uniform across blocks at entry
    float2 c_reg = make_float2(0.f, 0.f);

    // ---- Prologue W: load this block's three weight tiles into smem --------
    {
        #pragma unroll
        for (int kb = 0; kb < 4; kb++) {
            #pragma unroll
            for (int it = 0; it < 2; it++) {
                int idx = it * 256 + tid;            // 512 = 2arr x 64row x 4cg
                int arr = idx >> 8, rem = idx & 255;
                int row = rem >> 2, c8 = (rem & 3) * 8;
                size_t roff = (size_t)(ntA * 64 + row) * XD;
                const __nv_bfloat16* srcO = (arr ? g_Wreclo : g_Wrechi)
                    + roff + kcA * 128 + kb * 32 + c8;
                const __nv_bfloat16* srcH = (arr ? g_Wreclo : g_Wrechi)
                    + roff + 512 + kcA * 128 + kb * 32 + c8;
                int doff = (kb * 2 * 64 + arr * 64 + row) * 40 + c8;
                *(uint4*)(&wAo[doff]) = *(const uint4*)srcO;
                *(uint4*)(&wAh[doff]) = *(const uint4*)srcH;
            }
        }
        #pragma unroll
        for (int kb = 0; kb < 3; kb++) {
            #pragma unroll
            for (int it = 0; it < 2; it++) {
                int idx = it * 256 + tid;
                int arr = idx >> 8, rem = idx & 255;
                int row = rem >> 2, c8 = (rem & 3) * 8;
                const __nv_bfloat16* src = (arr ? g_Wulo : g_Wuhi)
                    + (size_t)(ntE * 64 + row) * UD + kcE * 96 + kb * 32 + c8;
                *(uint4*)(&wE[(kb * 2 * 64 + arr * 64 + row) * 40 + c8]) =
                    *(const uint4*)src;
            }
        }
        __syncthreads();
    }

    // ---- Prologue P1: h0 / c0 / o0 k-split GEMMs (fp32, scratch region) ----
    if (bid < 16) {
        int nt = bid & 7, kc = bid >> 3;
        ull acc[4][4] = {{0ULL}};
        gemm_core64(q, NQ, W_h, NQ, nt * 64, kc * 256, 4, smem, tid, acc);
        store_part64(acc, kc, nt * 64, NH, tid);
    } else if (bid < 32) {
        int nt = (bid - 16) & 7, kc = (bid - 16) >> 3;
        ull acc[4][4] = {{0ULL}};
        gemm_core64(q, NQ, W_c, NQ, nt * 64, kc * 256, 4, smem, tid, acc);
        store_part64(acc, 2 + kc, nt * 64, NH, tid);
    } else if (bid < 96) {
        int nt = (bid - 32) & 7, kc = (bid - 32) >> 3;
        ull acc[4][4] = {{0ULL}};
        gemm_core64(globalf, 2 * FLOC, W_g2o, 2 * FLOC, nt * 64, kc * 256, 4,
                    smem, tid, acc);
        store_part64(acc, 4 + kc, nt * 64, NH, tid);
    }
    gbar(++ep);

    // ---- Prologue P2: reduce into states -----------------------------------
    if (bid < NB) {
        int b = bid, j = tid * 2;
        float2 h0 = make_float2(0.f, 0.f), c0 = h0;
        float2 o0 = *(const float2*)(b_g2o + j);
        #pragma unroll
        for (int s = 0; s < 2; s++) {
            float2 v = __ldcg((const float2*)(&g_P[((s << 6) + b) * NH + j]));
            h0.x += v.x; h0.y += v.y;
        }
        #pragma unroll
        for (int s = 2; s < 4; s++) {
            float2 v = __ldcg((const float2*)(&g_P[((s << 6) + b) * NH + j]));
            c0.x += v.x; c0.y += v.y;
        }
        #pragma unroll
        for (int s = 4; s < 12; s++) {
            float2 v = __ldcg((const float2*)(&g_P[((s << 6) + b) * NH + j]));
            o0.x += v.x; o0.y += v.y;
        }
        split2(h0.x, g_xhi[b * XD + NH + j],     g_xlo[b * XD + NH + j]);
        split2(h0.y, g_xhi[b * XD + NH + j + 1], g_xlo[b * XD + NH + j + 1]);
        split2(o0.x, g_xhi[b * XD + j],          g_xlo[b * XD + j]);
        split2(o0.y, g_xhi[b * XD + j + 1],      g_xlo[b * XD + j + 1]);
        c_reg = c0;
    }
    gbar(++ep);

    // ---- Prologue P3: A_full(0): o-slot kcA, h-slot 4+kcA -------------------
    {
        float acc[2][2][4];
        zacc<2>(acc);
        mma_res<64, 4>(g_xhi, g_xlo, XD, kcA * 128, wAo, smb, tid, acc);
        mma_store_t<2>(acc, g_P, kcA, ntA * 64, G4, tid);
        zacc<2>(acc);
        mma_res<64, 4>(g_xhi, g_xlo, XD, 512 + kcA * 128, wAh, smb, tid, acc);
        mma_store_t<2>(acc, g_P, 4 + kcA, ntA * 64, G4, tid);
    }
    gbar(++ep);

    for (int t = 0; t < NT; t++) {
        // ---- BD(t): LSTM cell + attention (block b = batch b) -------------
        if (bid < NB) {
            float* sh = smem;
            float* se = smem + 512;
            int b = bid, j = tid * 2;
            const float* gy = &g_gatesy[(t * NB + b) * G4];
            float2 gi = *(const float2*)(gy + j);
            float2 gf = *(const float2*)(gy + NH + j);
            float2 gg = *(const float2*)(gy + 2 * NH + j);
            float2 go = *(const float2*)(gy + 3 * NH + j);
            #pragma unroll
            for (int kc = 0; kc < 8; kc++) {
                const float* p = &g_P[(kc * 64 + b) * G4];
                float2 v;
                v = __ldcg((const float2*)(p + j));          gi.x += v.x; gi.y += v.y;
                v = __ldcg((const float2*)(p + NH + j));     gf.x += v.x; gf.y += v.y;
                v = __ldcg((const float2*)(p + 2 * NH + j)); gg.x += v.x; gg.y += v.y;
                v = __ldcg((const float2*)(p + 3 * NH + j)); go.x += v.x; go.y += v.y;
            }
            float2 h2;
            {
                float ig = 1.f / (1.f + expf(-gi.x));
                float fg = 1.f / (1.f + expf(-gf.x));
                float gt = tanhf(gg.x);
                float og = 1.f / (1.f + expf(-go.x));
                c_reg.x = fg * c_reg.x + ig * gt;
                h2.x = og * tanhf(c_reg.x);
            }
            {
                float ig = 1.f / (1.f + expf(-gi.y));
                float fg = 1.f / (1.f + expf(-gf.y));
                float gt = tanhf(gg.y);
                float og = 1.f / (1.f + expf(-go.y));
                c_reg.y = fg * c_reg.y + ig * gt;
                h2.y = og * tanhf(c_reg.y);
            }
            *(float2*)(sh + j) = h2;
            split2(h2.x, g_xhi[b * XD + NH + j],     g_xlo[b * XD + NH + j]);
            split2(h2.y, g_xhi[b * XD + NH + j + 1], g_xlo[b * XD + NH + j + 1]);
            split2(h2.x, g_uhi[b * UD + FLOC + j],     g_ulo[b * UD + FLOC + j]);
            split2(h2.y, g_uhi[b * UD + FLOC + j + 1], g_ulo[b * UD + FLOC + j + 1]);
            __syncthreads();

            int warp = tid >> 5, lane = tid & 31;
            const float* pb = &g_attnproj[(size_t)b * NR * NH];
            for (int r = warp; r < NR; r += 8) {
                const float* pr = pb + r * NH;
                float s = 0.f;
                #pragma unroll
                for (int i = 0; i < 4; i++) {
                    float4 pv = *(const float4*)(pr + lane * 4 + i * 128);
                    float4 hv = *(const float4*)(sh + lane * 4 + i * 128);
                    s += pv.x * hv.x + pv.y * hv.y + pv.z * hv.z + pv.w * hv.w;
                }
                #pragma unroll
                for (int off = 16; off; off >>= 1)
                    s += __shfl_xor_sync(0xffffffffu, s, off);
                if (lane == 0) se[r] = s;
            }
            __syncthreads();
            if (tid < 32) {
                float v0 = (tid < NR) ? se[tid] : -1e30f;
                float v1 = (tid + 32 < NR) ? se[tid + 32] : -1e30f;
                float mx = fmaxf(v0, v1);
                #pragma unroll
                for (int off = 16; off; off >>= 1)
                    mx = fmaxf(mx, __shfl_xor_sync(0xffffffffu, mx, off));
                float e0 = (tid < NR) ? expf(v0 - mx) : 0.f;
                float e1 = (tid + 32 < NR) ? expf(v1 - mx) : 0.f;
                float sum = e0 + e1;
                #pragma unroll
                for (int off = 16; off; off >>= 1)
                    sum += __shfl_xor_sync(0xffffffffu, sum, off);
                float inv = 1.f / sum;
                if (tid < NR) se[tid] = e0 * inv;
                if (tid + 32 < NR) se[tid + 32] = e1 * inv;
            }
            __syncthreads();
            {
                int f0 = tid * 4;
                const float* lb = local + (size_t)b * NR * FLOC;
                float4 a = make_float4(0.f, 0.f, 0.f, 0.f);
                #pragma unroll 7
                for (int r = 0; r < NR; r++) {
                    float w = se[r];
                    float4 lv = *(const float4*)(lb + r * FLOC + f0);
                    a.x = fmaf(w, lv.x, a.x);
                    a.y = fmaf(w, lv.y, a.y);
                    a.z = fmaf(w, lv.z, a.z);
                    a.w = fmaf(w, lv.w, a.w);
                }
                split2(a.x, g_uhi[b * UD + f0 + 0], g_ulo[b * UD + f0 + 0]);
                split2(a.y, g_uhi[b * UD + f0 + 1], g_ulo[b * UD + f0 + 1]);
                split2(a.z, g_uhi[b * UD + f0 + 2], g_ulo[b * UD + f0 + 2]);
                split2(a.w, g_uhi[b * UD + f0 + 3], g_ulo[b * UD + f0 + 3]);
            }
        }
        gbar(++ep);

        // ---- Phase2: every block: A_h(t+1) then E(t) ------------------------
        {
            if (t + 1 < NT) {
                float acc[2][2][4];
                zacc<2>(acc);
                mma_res<64, 4>(g_xhi, g_xlo, XD, 512 + kcA * 128, wAh, smb, tid, acc);
                mma_store_t<2>(acc, g_P, 4 + kcA, ntA * 64, G4, tid);
            }
            float acc[2][2][4];
            zacc<2>(acc);
            mma_res<64, 3>(g_uhi, g_ulo, UD, kcE * 96, wE, smb, tid, acc);
            mma_store_t<2>(acc, g_Q, kcE, ntE * 64, NH, tid);
        }
        gbar(++ep);

        // ---- F(t): reduce 16 E-partials + tanh -> o_t -----------------------
        {
            int idx = bid * 256 + tid;
            int b = idx >> 9, n = idx & 511;
            float s = b_u[n];
            #pragma unroll
            for (int kc = 0; kc < 16; kc++)
                s += __ldcg(&g_Q[(kc * 64 + b) * NH + n]);
            s = tanhf(s);
            __nv_bfloat16 hi, lo;
            split2(s, hi, lo);
            g_xhi[b * XD + n] = hi;
            g_xlo[b * XD + n] = lo;
            int oi = (t * NB + b) * NH + n;
            g_ohi[oi] = hi;
            g_olo[oi] = lo;
        }
        gbar(++ep);

        // ---- Phase4: every block: A_o(t+1) ----------------------------------
        if (t + 1 < NT) {
            float acc[2][2][4];
            zacc<2>(acc);
            mma_res<64, 4>(g_xhi, g_xlo, XD, kcA * 128, wAo, smb, tid, acc);
            mma_store_t<2>(acc, g_P, kcA, ntA * 64, G4, tid);
        }
        gbar(++ep);
    }
}

// ---------------- general f32-input mma GEMM (attnproj / gatesy) ------------
__global__ void __launch_bounds__(256, 2)
gmma_kernel(const float* __restrict__ X, int ldx, int Mtot,
            const float* __restrict__ W, int ldw, int Nw, int K,
            const float* __restrict__ b1, const float* __restrict__ b2,
            float* __restrict__ out, int ldo)
{
    __shared__ __nv_bfloat16 sA[2][128][40];
    __shared__ __nv_bfloat16 sB[2][128][40];
    const int tid = threadIdx.x;
    const int lane = tid & 31, wid = tid >> 5;
    const int mw = wid >> 2, nw = wid & 3;
    const int gid = lane >> 2, cid = lane & 3;
    const int n0 = blockIdx.x * 128;
    const int m0 = blockIdx.y * 128;

    float acc[4][4][4];
    #pragma unroll
    for (int f = 0; f < 4; f++)
        #pragma unroll
        for (int g = 0; g < 4; g++)
            #pragma unroll
            for (int e = 0; e < 4; e++) acc[f][g][e] = 0.f;

    for (int kb = 0; kb < K; kb += 32) {
        #pragma unroll
        for (int it = 0; it < 8; it++) {
            int idx = it * 256 + tid;
            int isB = idx >> 10, rem = idx & 1023;
            int row = rem >> 3, c4 = (rem & 7) * 4;
            float4 v = make_float4(0.f, 0.f, 0.f, 0.f);
            if (!isB) {
                int gm = m0 + row;
                if (gm < Mtot) v = *(const float4*)(X + (size_t)gm * ldx + kb + c4);
            } else {
                int wr = n0 + row;
                if (wr < Nw) v = *(const float4*)(W + (size_t)wr * ldw + kb + c4);
            }
            __nv_bfloat16 h0, l0, h1, l1, h2, l2, h3, l3;
            split2(v.x, h0, l0); split2(v.y, h1, l1);
            split2(v.z, h2, l2); split2(v.w, h3, l3);
            uint2 hp = make_uint2(pbf2(h0, h1), pbf2(h2, h3));
            uint2 lp = make_uint2(pbf2(l0, l1), pbf2(l2, l3));
            if (!isB) {
                *(uint2*)(&sA[0][row][c4]) = hp;
                *(uint2*)(&sA[1][row][c4]) = lp;
            } else {
                *(uint2*)(&sB[0][row][c4]) = hp;
                *(uint2*)(&sB[1][row][c4]) = lp;
            }
        }
        __syncthreads();
        #pragma unroll
        for (int kh = 0; kh < 2; kh++) {
            int k0 = kh * 16 + 2 * cid;
            uint32_t a[4][4], bh[4][2], bl[4][2];
            #pragma unroll
            for (int f = 0; f < 4; f++) {
                const __nv_bfloat16* ap = &sA[0][mw * 64 + f * 16 + gid][k0];
                a[f][0] = *(const uint32_t*)ap;
                a[f][1] = *(const uint32_t*)(ap + 8 * 40);
                a[f][2] = *(const uint32_t*)(ap + 8);
                a[f][3] = *(const uint32_t*)(ap + 8 * 40 + 8);
            }
            #pragma unroll
            for (int g = 0; g < 4; g++) {
                const __nv_bfloat16* bp = &sB[0][nw * 32 + g * 8 + gid][k0];
                bh[g][0] = *(const uint32_t*)bp;
                bh[g][1] = *(const uint32_t*)(bp + 8);
                const __nv_bfloat16* bq = &sB[1][nw * 32 + g * 8 + gid][k0];
                bl[g][0] = *(const uint32_t*)bq;
                bl[g][1] = *(const uint32_t*)(bq + 8);
            }
            #pragma unroll
            for (int f = 0; f < 4; f++)
                #pragma unroll
                for (int g = 0; g < 4; g++) {
                    MMA_BF16(acc[f][g], a[f], bh[g]);
                    MMA_BF16(acc[f][g], a[f], bl[g]);
                }
            #pragma unroll
            for (int f = 0; f < 4; f++) {
                const __nv_bfloat16* ap = &sA[1][mw * 64 + f * 16 + gid][k0];
                a[f][0] = *(const uint32_t*)ap;
                a[f][1] = *(const uint32_t*)(ap + 8 * 40);
                a[f][2] = *(const uint32_t*)(ap + 8);
                a[f][3] = *(const uint32_t*)(ap + 8 * 40 + 8);
            }
            #pragma unroll
            for (int f = 0; f < 4; f++)
                #pragma unroll
                for (int g = 0; g < 4; g++)
                    MMA_BF16(acc[f][g], a[f], bh[g]);
        }
        __syncthreads();
    }

    float2 bias[4];
    #pragma unroll
    for (int g = 0; g < 4; g++) {
        int n = n0 + nw * 32 + g * 8 + 2 * cid;
        float2 bv = make_float2(0.f, 0.f);
        if (n < Nw) {
            if (b1) { bv.x += b1[n]; bv.y += b1[n + 1]; }
            if (b2) { bv.x += b2[n]; bv.y += b2[n + 1]; }
        }
        bias[g] = bv;
    }
    #pragma unroll
    for (int f = 0; f < 4; f++) {
        #pragma unroll
        for (int half = 0; half < 2; half++) {
            int m = m0 + mw * 64 + f * 16 + gid + half * 8;
            if (m < Mtot) {
                float* orow = out + (size_t)m * ldo;
                #pragma unroll
                for (int g = 0; g < 4; g++) {
                    int n = n0 + nw * 32 + g * 8 + 2 * cid;
                    if (n < Nw) {
                        float2 v;
                        v.x = acc[f][g][half * 2 + 0] + bias[g].x;
                        v.y = acc[f][g][half * 2 + 1] + bias[g].y;
                        *(float2*)(orow + n) = v;
                    }
                }
            }
        }
    }
}

// ---------------- vocab GEMM via mma.sync bf16 hi/lo split ------------------
__global__ void __launch_bounds__(256, 2)
vocab_mma_kernel(const float* __restrict__ b_vocab, float* __restrict__ out)
{
    __shared__ __nv_bfloat16 sA[2][128][40];
    __shared__ __nv_bfloat16 sB[2][128][40];
    const int tid = threadIdx.x;
    const int lane = tid & 31, wid = tid >> 5;
    const int mw = wid >> 2, nw = wid & 3;
    const int gid = lane >> 2, cid = lane & 3;
    const int n0 = blockIdx.x * 128;
    const int m0 = blockIdx.y * 128;

    float acc[4][4][4];
    #pragma unroll
    for (int f = 0; f < 4; f++)
        #pragma unroll
        for (int g = 0; g < 4; g++)
            #pragma unroll
            for (int e = 0; e < 4; e++) acc[f][g][e] = 0.f;

    for (int kb = 0; kb < NH; kb += 32) {
        #pragma unroll
        for (int it = 0; it < 8; it++) {
            int idx = it * 256 + tid;
            int arr = idx >> 9;
            int rem = idx & 511;
            int row = rem >> 2, c16 = (rem & 3) * 8;
            uint4 v;
            if (arr == 0) {
                v = *(const uint4*)(&g_ohi[(size_t)(m0 + row) * NH + kb + c16]);
                *(uint4*)(&sA[0][row][c16]) = v;
            } else if (arr == 1) {
                v = *(const uint4*)(&g_olo[(size_t)(m0 + row) * NH + kb + c16]);
                *(uint4*)(&sA[1][row][c16]) = v;
            } else {
                int nr = n0 + row;
                const __nv_bfloat16* src = (arr == 2) ? g_Wvhi : g_Wvlo;
                v = (nr < NV) ? *(const uint4*)(&src[(size_t)nr * NH + kb + c16])
                              : make_uint4(0, 0, 0, 0);
                *(uint4*)(&sB[arr - 2][row][c16]) = v;
            }
        }
        __syncthreads();
        #pragma unroll
        for (int kh = 0; kh < 2; kh++) {
            int k0 = kh * 16 + 2 * cid;
            uint32_t a[4][4], bh[4][2], bl[4][2];
            #pragma unroll
            for (int f = 0; f < 4; f++) {
                const __nv_bfloat16* ap = &sA[0][mw * 64 + f * 16 + gid][k0];
                a[f][0] = *(const uint32_t*)ap;
                a[f][1] = *(const uint32_t*)(ap + 8 * 40);
                a[f][2] = *(const uint32_t*)(ap + 8);
                a[f][3] = *(const uint32_t*)(ap + 8 * 40 + 8);
            }
            #pragma unroll
            for (int g = 0; g < 4; g++) {
                const __nv_bfloat16* bp = &sB[0][nw * 32 + g * 8 + gid][k0];
                bh[g][0] = *(const uint32_t*)bp;
                bh[g][1] = *(const uint32_t*)(bp + 8);
                const __nv_bfloat16* bq = &sB[1][nw * 32 + g * 8 + gid][k0];
                bl[g][0] = *(const uint32_t*)bq;
                bl[g][1] = *(const uint32_t*)(bq + 8);
            }
            #pragma unroll
            for (int f = 0; f < 4; f++)
                #pragma unroll
                for (int g = 0; g < 4; g++) {
                    MMA_BF16(acc[f][g], a[f], bh[g]);
                    MMA_BF16(acc[f][g], a[f], bl[g]);
                }
            #pragma unroll
            for (int f = 0; f < 4; f++) {
                const __nv_bfloat16* ap = &sA[1][mw * 64 + f * 16 + gid][k0];
                a[f][0] = *(const uint32_t*)ap;
                a[f][1] = *(const uint32_t*)(ap + 8 * 40);
                a[f][2] = *(const uint32_t*)(ap + 8);
                a[f][3] = *(const uint32_t*)(ap + 8 * 40 + 8);
            }
            #pragma unroll
            for (int f = 0; f < 4; f++)
                #pragma unroll
                for (int g = 0; g < 4; g++)
                    MMA_BF16(acc[f][g], a[f], bh[g]);
        }
        __syncthreads();
    }

    float2 bias[4];
    #pragma unroll
    for (int g = 0; g < 4; g++) {
        int n = n0 + nw * 32 + g * 8 + 2 * cid;
        bias[g] = (n < NV) ? *(const float2*)(b_vocab + n) : make_float2(0.f, 0.f);
    }
    #pragma unroll
    for (int f = 0; f < 4; f++) {
        int mr = m0 + mw * 64 + f * 16 + gid;
        #pragma unroll
        for (int half = 0; half < 2; half++) {
            int m = mr + half * 8;
            int b = m & 63, t = m >> 6;
            float* orow = out + ((size_t)b * NT + t) * NV;
            #pragma unroll
            for (int g = 0; g < 4; g++) {
                int n = n0 + nw * 32 + g * 8 + 2 * cid;
                if (n < NV) {
                    float2 v;
                    v.x = acc[f][g][half * 2 + 0] + bias[g].x;
                    v.y = acc[f][g][half * 2 + 1] + bias[g].y;
                    *(float2*)(orow + n) = v;
                }
            }
        }
    }
}

// ---------------------------------------------------------------------------
extern "C" void kernel_launch(void* const* d_in, const int* in_sizes, int n_in,
                              void* d_out, int out_size)
{
    const float* local   = (const float*)d_in[0];
    const float* globalf = (const float*)d_in[1];
    const float* q       = (const float*)d_in[2];
    const int*   answers = (const int*)d_in[3];
    const float* emb     = (const float*)d_in[4];
    const float* W_g2o   = (const float*)d_in[5];
    const float* b_g2o   = (const float*)d_in[6];
    const float* W_h     = (const float*)d_in[7];
    const float* W_c     = (const float*)d_in[8];
    const float* W_ih    = (const float*)d_in[9];
    const float* W_hh    = (const float*)d_in[10];
    const float* b_ih    = (const float*)d_in[11];
    const float* b_hh    = (const float*)d_in[12];
    const float* W_attn  = (const float*)d_in[13];
    const float* W_u     = (const float*)d_in[14];
    const float* b_u     = (const float*)d_in[15];
    const float* W_vocab = (const float*)d_in[16];
    const float* b_vocab = (const float*)d_in[17];
    float* out = (float*)d_out;

    cudaFuncSetAttribute(loop_kernel, cudaFuncAttributeMaxDynamicSharedMemorySize, SMEMB);

    float* d_gatesy;   cudaGetSymbolAddress((void**)&d_gatesy,   g_gatesy);
    float* d_attnproj; cudaGetSymbolAddress((void**)&d_attnproj, g_attnproj);
    float* d_yseq;     cudaGetSymbolAddress((void**)&d_yseq,     g_yseq);

    // 1) weight hi/lo splits + embedding gather
    prep_kernel<<<512, 256>>>(W_ih, W_hh, W_u, emb, answers, W_vocab);

    // 2) attn_proj = local @ W_attn^T   (M=3136, N=512, K=1024) via mma
    gmma_kernel<<<dim3(4, 25), 256>>>(
        local, FLOC, NB * NR, W_attn, FLOC, NH, FLOC,
        nullptr, nullptr, d_attnproj, NH);

    // 3) gates_y = yseq @ W_ih[:, :256]^T + b_ih + b_hh  (M=2048,N=2048,K=256)
    gmma_kernel<<<dim3(16, 16), 256>>>(
        d_yseq, NE, NT * NB, W_ih, 768, G4, NE,
        b_ih, b_hh, d_gatesy, G4);

    // 4) init states + pipelined recurrence, all tiles SM-resident, full-grid
    loop_kernel<<<NBLK, 256, SMEMB>>>(local, b_u, q, W_h, W_c,
                                      globalf, W_g2o, b_g2o);

    // 5) logits = o_all @ W_vocab^T + b_vocab  (bf16 hi/lo mma.sync)
    vocab_mma_kernel<<<dim3((NV + 127) / 128, (NT * NB) / 128), 256>>>(
        b_vocab, out);
}

// round 16
// speedup vs baseline: 1.2792x; 1.2792x over previous
#include <cuda_runtime.h>
#include <cuda_bf16.h>
#include <math.h>
#include <stdint.h>

#define NB 64
#define NT 32
#define NR 49
#define FLOC 1024
#define NQ 512
#define NE 256
#define NH 512
#define NV 10000
#define G4 2048   // 4*HID
#define XD 1024   // [o(512), h(512)]
#define UD 1536   // [a(1024), h(512)]
#define NBLK 128  // persistent kernel grid (co-resident)

typedef unsigned long long ull;

// loop smem layout (bytes): [0, 33280) scratch/staging union, then resident
// tiles: A_o (40960), A_h (40960), E (30720)
#define SCRATCH_B 33280
#define WAO_B     40960   // 4kb x 2(hi/lo) x 64row x 40 x 2B
#define WAH_B     40960
#define WE_B      30720   // 3kb x 2 x 64row x 40 x 2B
#define SMEMB     (SCRATCH_B + WAO_B + WAH_B + WE_B)

#define VQSMEM    81920   // vocab kernel: 2 x (sA 20480 + sB 20480) bytes

// ---------------- scratch (device globals; no allocation allowed) ----------
__device__ __nv_bfloat16 g_Wrechi[G4 * XD];   // recurrent weight hi/lo
__device__ __nv_bfloat16 g_Wreclo[G4 * XD];
__device__ __nv_bfloat16 g_Wuhi[NH * UD];     // W_u hi/lo
__device__ __nv_bfloat16 g_Wulo[NH * UD];
__device__ __nv_bfloat16 g_Wvhi[NV * NH];     // W_vocab hi/lo
__device__ __nv_bfloat16 g_Wvlo[NV * NH];
__device__ float g_yseq[NT * NB * NE];        // teacher-forced input embeddings
__device__ float g_gatesy[NT * NB * G4];      // y @ W_ihy^T + b_ih + b_hh
__device__ float g_attnproj[NB * NR * NH];    // local @ W_attn^T  [b][r][h]
__device__ __nv_bfloat16 g_xhi[NB * XD];      // [o,h] activations hi/lo
__device__ __nv_bfloat16 g_xlo[NB * XD];
__device__ __nv_bfloat16 g_uhi[NB * UD];      // [a,h] activations hi/lo
__device__ __nv_bfloat16 g_ulo[NB * UD];
__device__ __nv_bfloat16 g_ohi[NT * NB * NH]; // all o_t hi/lo (vocab A)
__device__ __nv_bfloat16 g_olo[NT * NB * NH];
__device__ float g_P[12 * NB * G4];           // A-stage k-split partials
__device__ float g_Q[16 * NB * NH];           // E-stage k-split partials
__device__ volatile unsigned int g_arr[NBLK];
__device__ volatile unsigned int g_rel;

// ---------------- helpers ----------------------------------------------------
__device__ __forceinline__ ull pack2(float a, float b) {
    ull r; asm("mov.b64 %0, {%1, %2};" : "=l"(r) : "f"(a), "f"(b)); return r;
}
__device__ __forceinline__ float2 unpack2(ull v) {
    float2 r; asm("mov.b64 {%0, %1}, %2;" : "=f"(r.x), "=f"(r.y) : "l"(v)); return r;
}
__device__ __forceinline__ void ffma2(ull& acc, ull a, ull b) {
    asm("fma.rn.f32x2 %0, %1, %2, %0;" : "+l"(acc) : "l"(a), "l"(b));
}
__device__ __forceinline__ void split2(float v, __nv_bfloat16& hi, __nv_bfloat16& lo) {
    hi = __float2bfloat16(v);
    lo = __float2bfloat16(v - __bfloat162float(hi));
}
__device__ __forceinline__ uint32_t pbf2(__nv_bfloat16 a, __nv_bfloat16 b) {
    __nv_bfloat162 t = __halves2bfloat162(a, b);
    return *(uint32_t*)&t;
}

#define MMA_BF16(c, a, b) \
    asm volatile("mma.sync.aligned.m16n8k16.row.col.f32.bf16.bf16.f32 " \
        "{%0,%1,%2,%3}, {%4,%5,%6,%7}, {%8,%9}, {%0,%1,%2,%3};" \
        : "+f"((c)[0]), "+f"((c)[1]), "+f"((c)[2]), "+f"((c)[3]) \
        : "r"((a)[0]), "r"((a)[1]), "r"((a)[2]), "r"((a)[3]), \
          "r"((b)[0]), "r"((b)[1]))

// ---------------- coordinator grid barrier (proven r12/r13 design) ----------
// Arrivals: per-block flag store. Block 0 gathers 128 flags, publishes g_rel;
// other blocks spin on the single broadcast-friendly g_rel address.
__device__ __forceinline__ void gbar(unsigned int e) {
    __syncthreads();
    if (blockIdx.x == 0) {
        __threadfence();
        if (threadIdx.x == 0) g_arr[0] = e;
        if (threadIdx.x < NBLK) {
            while (g_arr[threadIdx.x] < e) { }
        }
        __threadfence();
        __syncthreads();
        if (threadIdx.x == 0) g_rel = e;
    } else {
        if (threadIdx.x == 0) {
            __threadfence();
            g_arr[blockIdx.x] = e;
            while (g_rel < e) { }
            __threadfence();
        }
        __syncthreads();
    }
}

// ---------------- fp32 GEMM core (prologue only): 64(m) x 64(n) -------------
__device__ __forceinline__ void gemm_core64(
    const float* __restrict__ X, int ldx,
    const float* __restrict__ W, int ldw,
    int n0, int kbase, int kSteps64,
    float* smem, int tid, ull acc[4][4])
{
    float* xs = smem;
    float* ws = smem + 64 * 65;
    int tx = tid & 15, ty = tid >> 4;
    for (int kb = 0; kb < kSteps64; kb++) {
        int kpos = kbase + kb * 64;
        #pragma unroll
        for (int it = 0; it < 4; it++) {
            int idx = it * 256 + tid;
            int row = idx >> 4, kq = (idx & 15) << 2;
            float4 v = __ldcg((const float4*)(X + row * ldx + kpos + kq));
            float* d = &xs[row * 65 + kq];
            d[0] = v.x; d[1] = v.y; d[2] = v.z; d[3] = v.w;
            float4 w = *(const float4*)(W + (size_t)(n0 + row) * ldw + kpos + kq);
            float* e = &ws[row * 65 + kq];
            e[0] = w.x; e[1] = w.y; e[2] = w.z; e[3] = w.w;
        }
        __syncthreads();
        #pragma unroll 8
        for (int k = 0; k < 64; k++) {
            ull xd[4];
            #pragma unroll
            for (int i = 0; i < 4; i++) {
                float x = xs[(ty * 4 + i) * 65 + k];
                xd[i] = pack2(x, x);
            }
            float a0 = ws[(tx * 4 + 0) * 65 + k];
            float a1 = ws[(tx * 4 + 1) * 65 + k];
            float a2 = ws[(tx * 4 + 2) * 65 + k];
            float a3 = ws[(tx * 4 + 3) * 65 + k];
            ull wA0 = pack2(a0, a1), wA1 = pack2(a2, a3);
            #pragma unroll
            for (int i = 0; i < 4; i++) {
                ffma2(acc[i][0], xd[i], wA0);
                ffma2(acc[i][1], xd[i], wA1);
            }
        }
        __syncthreads();
    }
}

__device__ __forceinline__ void store_part64(ull acc[4][4], int kc, int n0, int N, int tid)
{
    int tx = tid & 15, ty = tid >> 4;
    #pragma unroll
    for (int i = 0; i < 4; i++) {
        int m = ty * 4 + i;
        float* dst = &g_P[((kc << 6) + m) * N + n0];
        #pragma unroll
        for (int jj = 0; jj < 2; jj++)
            *(float2*)(dst + tx * 4 + jj * 2) = unpack2(acc[i][jj]);
    }
}

// ---------------- resident-weight bf16 mma core -----------------------------
template<int BN, int KSTEPS>
__device__ __forceinline__ void mma_res(
    const __nv_bfloat16* __restrict__ Ahi, const __nv_bfloat16* __restrict__ Alo,
    int lda, int kbase,
    const __nv_bfloat16* __restrict__ wRes,
    __nv_bfloat16* sA, int tid, float (&acc)[2][BN / 32][4])
{
    constexpr int NG = BN / 32;
    constexpr int ABUF = 2 * 64 * 40;
    const int lane = tid & 31, wid = tid >> 5;
    const int mw = wid >> 2, nw = wid & 3;
    const int gid = lane >> 2, cid = lane & 3;

    const int pidx0 = tid, pidx1 = 256 + tid;
    const int arr0 = pidx0 >> 8, row0 = (pidx0 & 255) >> 2, c80 = ((pidx0 & 255) & 3) * 8;
    const int arr1 = pidx1 >> 8, row1 = (pidx1 & 255) >> 2, c81 = ((pidx1 & 255) & 3) * 8;
    const __nv_bfloat16* a0base = (arr0 ? Alo : Ahi) + (size_t)row0 * lda + kbase + c80;
    const __nv_bfloat16* a1base = (arr1 ? Alo : Ahi) + (size_t)row1 * lda + kbase + c81;
    const int s0off = (arr0 * 64 + row0) * 40 + c80;
    const int s1off = (arr1 * 64 + row1) * 40 + c81;

    *(uint4*)(&sA[s0off]) = __ldcg((const uint4*)a0base);
    *(uint4*)(&sA[s1off]) = __ldcg((const uint4*)a1base);
    __syncthreads();

    for (int kb = 0; kb < KSTEPS; kb++) {
        uint4 pre0, pre1;
        bool haveNext = (kb + 1 < KSTEPS);
        if (haveNext) {
            pre0 = __ldcg((const uint4*)(a0base + (kb + 1) * 32));
            pre1 = __ldcg((const uint4*)(a1base + (kb + 1) * 32));
        }
        const __nv_bfloat16* sAc = sA + (kb & 1) * ABUF;
        const __nv_bfloat16* sB = wRes + (size_t)kb * (2 * BN * 40);
        #pragma unroll
        for (int kh = 0; kh < 2; kh++) {
            int k0 = kh * 16 + 2 * cid;
            uint32_t a[2][4], bh[NG][2], bl[NG][2];
            #pragma unroll
            for (int f = 0; f < 2; f++) {
                const __nv_bfloat16* ap = &sAc[(mw * 32 + f * 16 + gid) * 40 + k0];
                a[f][0] = *(const uint32_t*)ap;
                a[f][1] = *(const uint32_t*)(ap + 8 * 40);
                a[f][2] = *(const uint32_t*)(ap + 8);
                a[f][3] = *(const uint32_t*)(ap + 8 * 40 + 8);
            }
            #pragma unroll
            for (int g = 0; g < NG; g++) {
                const __nv_bfloat16* bp = &sB[(nw * (BN / 4) + g * 8 + gid) * 40 + k0];
                bh[g][0] = *(const uint32_t*)bp;
                bh[g][1] = *(const uint32_t*)(bp + 8);
                const __nv_bfloat16* bq = bp + (size_t)BN * 40;
                bl[g][0] = *(const uint32_t*)bq;
                bl[g][1] = *(const uint32_t*)(bq + 8);
            }
            #pragma unroll
            for (int f = 0; f < 2; f++)
                #pragma unroll
                for (int g = 0; g < NG; g++) {
                    MMA_BF16(acc[f][g], a[f], bh[g]);
                    MMA_BF16(acc[f][g], a[f], bl[g]);
                }
            #pragma unroll
            for (int f = 0; f < 2; f++) {
                const __nv_bfloat16* ap = &sAc[(64 + mw * 32 + f * 16 + gid) * 40 + k0];
                a[f][0] = *(const uint32_t*)ap;
                a[f][1] = *(const uint32_t*)(ap + 8 * 40);
                a[f][2] = *(const uint32_t*)(ap + 8);
                a[f][3] = *(const uint32_t*)(ap + 8 * 40 + 8);
            }
            #pragma unroll
            for (int f = 0; f < 2; f++)
                #pragma unroll
                for (int g = 0; g < NG; g++)
                    MMA_BF16(acc[f][g], a[f], bh[g]);
        }
        if (haveNext) {
            __nv_bfloat16* sAn = sA + ((kb + 1) & 1) * ABUF;
            *(uint4*)(&sAn[s0off]) = pre0;
            *(uint4*)(&sAn[s1off]) = pre1;
        }
        __syncthreads();
    }
}

template<int NG>
__device__ __forceinline__ void mma_store_t(float (&acc)[2][NG][4], float* buf,
                                            int slot, int n0, int N, int tid)
{
    const int lane = tid & 31, wid = tid >> 5;
    const int mw = wid >> 2, nw = wid & 3;
    const int gid = lane >> 2, cid = lane & 3;
    #pragma unroll
    for (int f = 0; f < 2; f++)
        #pragma unroll
        for (int half = 0; half < 2; half++) {
            int m = mw * 32 + f * 16 + gid + half * 8;
            float* dst = buf + ((slot << 6) + m) * N + n0 + nw * 8 * NG + 2 * cid;
            #pragma unroll
            for (int g = 0; g < NG; g++)
                *(float2*)(dst + g * 8) =
                    make_float2(acc[f][g][half * 2], acc[f][g][half * 2 + 1]);
        }
}

template<int NG>
__device__ __forceinline__ void zacc(float (&acc)[2][NG][4]) {
    #pragma unroll
    for (int f = 0; f < 2; f++)
        #pragma unroll
        for (int g = 0; g < NG; g++)
            #pragma unroll
            for (int e = 0; e < 4; e++) acc[f][g][e] = 0.f;
}

// ---------------- one-time prep: weight splits + embed gather ---------------
__global__ void prep_kernel(const float* __restrict__ W_ih,
                            const float* __restrict__ W_hh,
                            const float* __restrict__ W_u,
                            const float* __restrict__ emb,
                            const int*   __restrict__ answers,
                            const float* __restrict__ W_vocab)
{
    int stride = gridDim.x * blockDim.x;
    int tid0 = blockIdx.x * blockDim.x + threadIdx.x;
    for (int i = tid0; i < G4 * XD; i += stride) {
        int n = i >> 10, k = i & 1023;
        float w = (k < NH) ? W_ih[n * 768 + 256 + k] : W_hh[n * NH + (k - NH)];
        split2(w, g_Wrechi[i], g_Wreclo[i]);
    }
    for (int i = tid0; i < NH * UD; i += stride)
        split2(W_u[i], g_Wuhi[i], g_Wulo[i]);
    for (int i = tid0; i < NV * NH; i += stride)
        split2(W_vocab[i], g_Wvhi[i], g_Wvlo[i]);
    for (int i = tid0; i < NT * NB * NE; i += stride) {
        int m = i >> 8, e = i & 255;
        int t = m >> 6, b = m & 63;
        int tok = (t == 0) ? 1 : answers[b * NT + (t - 1)];
        g_yseq[i] = emb[tok * NE + e];
    }
}

// ---------------- persistent recurrent-loop kernel -------------------------
__global__ void __launch_bounds__(256, 1)
loop_kernel(const float* __restrict__ local,
            const float* __restrict__ b_u,
            const float* __restrict__ q,
            const float* __restrict__ W_h,
            const float* __restrict__ W_c,
            const float* __restrict__ globalf,
            const float* __restrict__ W_g2o,
            const float* __restrict__ b_g2o)
{
    extern __shared__ float smem[];
    __nv_bfloat16* smb = (__nv_bfloat16*)smem;              // staging (bf16 view)
    __nv_bfloat16* wAo = smb + SCRATCH_B / 2;               // resident A o-tile
    __nv_bfloat16* wAh = smb + (SCRATCH_B + WAO_B) / 2;     // resident A h-tile
    __nv_bfloat16* wE  = smb + (SCRATCH_B + WAO_B + WAH_B) / 2;  // resident E tile
    const int bid = blockIdx.x;
    const int tid = threadIdx.x;
    const int ntA = bid & 31, kcA = bid >> 5;     // A tiles: 64n x 128k
    const int ntE = bid & 7,  kcE = bid >> 3;     // E tile : 64n x 96k
    unsigned int ep = g_rel;                      // uniform at entry
    float2 c_reg = make_float2(0.f, 0.f);

    // ---- Prologue W: load this block's three weight tiles into smem --------
    {
        #pragma unroll
        for (int kb = 0; kb < 4; kb++) {
            #pragma unroll
            for (int it = 0; it < 2; it++) {
                int idx = it * 256 + tid;            // 512 = 2arr x 64row x 4cg
                int arr = idx >> 8, rem = idx & 255;
                int row = rem >> 2, c8 = (rem & 3) * 8;
                size_t roff = (size_t)(ntA * 64 + row) * XD;
                const __nv_bfloat16* srcO = (arr ? g_Wreclo : g_Wrechi)
                    + roff + kcA * 128 + kb * 32 + c8;
                const __nv_bfloat16* srcH = (arr ? g_Wreclo : g_Wrechi)
                    + roff + 512 + kcA * 128 + kb * 32 + c8;
                int doff = (kb * 2 * 64 + arr * 64 + row) * 40 + c8;
                *(uint4*)(&wAo[doff]) = *(const uint4*)srcO;
                *(uint4*)(&wAh[doff]) = *(const uint4*)srcH;
            }
        }
        #pragma unroll
        for (int kb = 0; kb < 3; kb++) {
            #pragma unroll
            for (int it = 0; it < 2; it++) {
                int idx = it * 256 + tid;
                int arr = idx >> 8, rem = idx & 255;
                int row = rem >> 2, c8 = (rem & 3) * 8;
                const __nv_bfloat16* src = (arr ? g_Wulo : g_Wuhi)
                    + (size_t)(ntE * 64 + row) * UD + kcE * 96 + kb * 32 + c8;
                *(uint4*)(&wE[(kb * 2 * 64 + arr * 64 + row) * 40 + c8]) =
                    *(const uint4*)src;
            }
        }
        __syncthreads();
    }

    // ---- Prologue P1: h0 / c0 / o0 k-split GEMMs (fp32, scratch region) ----
    if (bid < 16) {
        int nt = bid & 7, kc = bid >> 3;
        ull acc[4][4] = {{0ULL}};
        gemm_core64(q, NQ, W_h, NQ, nt * 64, kc * 256, 4, smem, tid, acc);
        store_part64(acc, kc, nt * 64, NH, tid);
    } else if (bid < 32) {
        int nt = (bid - 16) & 7, kc = (bid - 16) >> 3;
        ull acc[4][4] = {{0ULL}};
        gemm_core64(q, NQ, W_c, NQ, nt * 64, kc * 256, 4, smem, tid, acc);
        store_part64(acc, 2 + kc, nt * 64, NH, tid);
    } else if (bid < 96) {
        int nt = (bid - 32) & 7, kc = (bid - 32) >> 3;
        ull acc[4][4] = {{0ULL}};
        gemm_core64(globalf, 2 * FLOC, W_g2o, 2 * FLOC, nt * 64, kc * 256, 4,
                    smem, tid, acc);
        store_part64(acc, 4 + kc, nt * 64, NH, tid);
    }
    gbar(++ep);

    // ---- Prologue P2: reduce into states -----------------------------------
    if (bid < NB) {
        int b = bid, j = tid * 2;
        float2 h0 = make_float2(0.f, 0.f), c0 = h0;
        float2 o0 = *(const float2*)(b_g2o + j);
        #pragma unroll
        for (int s = 0; s < 2; s++) {
            float2 v = __ldcg((const float2*)(&g_P[((s << 6) + b) * NH + j]));
            h0.x += v.x; h0.y += v.y;
        }
        #pragma unroll
        for (int s = 2; s < 4; s++) {
            float2 v = __ldcg((const float2*)(&g_P[((s << 6) + b) * NH + j]));
            c0.x += v.x; c0.y += v.y;
        }
        #pragma unroll
        for (int s = 4; s < 12; s++) {
            float2 v = __ldcg((const float2*)(&g_P[((s << 6) + b) * NH + j]));
            o0.x += v.x; o0.y += v.y;
        }
        split2(h0.x, g_xhi[b * XD + NH + j],     g_xlo[b * XD + NH + j]);
        split2(h0.y, g_xhi[b * XD + NH + j + 1], g_xlo[b * XD + NH + j + 1]);
        split2(o0.x, g_xhi[b * XD + j],          g_xlo[b * XD + j]);
        split2(o0.y, g_xhi[b * XD + j + 1],      g_xlo[b * XD + j + 1]);
        c_reg = c0;
    }
    gbar(++ep);

    // ---- Prologue P3: A_full(0): o-slot kcA, h-slot 4+kcA -------------------
    {
        float acc[2][2][4];
        zacc<2>(acc);
        mma_res<64, 4>(g_xhi, g_xlo, XD, kcA * 128, wAo, smb, tid, acc);
        mma_store_t<2>(acc, g_P, kcA, ntA * 64, G4, tid);
        zacc<2>(acc);
        mma_res<64, 4>(g_xhi, g_xlo, XD, 512 + kcA * 128, wAh, smb, tid, acc);
        mma_store_t<2>(acc, g_P, 4 + kcA, ntA * 64, G4, tid);
    }
    gbar(++ep);

    for (int t = 0; t < NT; t++) {
        // ---- BD(t): LSTM cell + attention (block b = batch b) -------------
        if (bid < NB) {
            float* sh = smem;
            float* se = smem + 512;
            int b = bid, j = tid * 2;
            const float* gy = &g_gatesy[(t * NB + b) * G4];
            float2 gi = *(const float2*)(gy + j);
            float2 gf = *(const float2*)(gy + NH + j);
            float2 gg = *(const float2*)(gy + 2 * NH + j);
            float2 go = *(const float2*)(gy + 3 * NH + j);
            #pragma unroll
            for (int kc = 0; kc < 8; kc++) {
                const float* p = &g_P[(kc * 64 + b) * G4];
                float2 v;
                v = __ldcg((const float2*)(p + j));          gi.x += v.x; gi.y += v.y;
                v = __ldcg((const float2*)(p + NH + j));     gf.x += v.x; gf.y += v.y;
                v = __ldcg((const float2*)(p + 2 * NH + j)); gg.x += v.x; gg.y += v.y;
                v = __ldcg((const float2*)(p + 3 * NH + j)); go.x += v.x; go.y += v.y;
            }
            float2 h2;
            {
                float ig = 1.f / (1.f + expf(-gi.x));
                float fg = 1.f / (1.f + expf(-gf.x));
                float gt = tanhf(gg.x);
                float og = 1.f / (1.f + expf(-go.x));
                c_reg.x = fg * c_reg.x + ig * gt;
                h2.x = og * tanhf(c_reg.x);
            }
            {
                float ig = 1.f / (1.f + expf(-gi.y));
                float fg = 1.f / (1.f + expf(-gf.y));
                float gt = tanhf(gg.y);
                float og = 1.f / (1.f + expf(-go.y));
                c_reg.y = fg * c_reg.y + ig * gt;
                h2.y = og * tanhf(c_reg.y);
            }
            *(float2*)(sh + j) = h2;
            split2(h2.x, g_xhi[b * XD + NH + j],     g_xlo[b * XD + NH + j]);
            split2(h2.y, g_xhi[b * XD + NH + j + 1], g_xlo[b * XD + NH + j + 1]);
            split2(h2.x, g_uhi[b * UD + FLOC + j],     g_ulo[b * UD + FLOC + j]);
            split2(h2.y, g_uhi[b * UD + FLOC + j + 1], g_ulo[b * UD + FLOC + j + 1]);
            __syncthreads();

            int warp = tid >> 5, lane = tid & 31;
            const float* pb = &g_attnproj[(size_t)b * NR * NH];
            for (int r = warp; r < NR; r += 8) {
                const float* pr = pb + r * NH;
                float s = 0.f;
                #pragma unroll
                for (int i = 0; i < 4; i++) {
                    float4 pv = *(const float4*)(pr + lane * 4 + i * 128);
                    float4 hv = *(const float4*)(sh + lane * 4 + i * 128);
                    s += pv.x * hv.x + pv.y * hv.y + pv.z * hv.z + pv.w * hv.w;
                }
                #pragma unroll
                for (int off = 16; off; off >>= 1)
                    s += __shfl_xor_sync(0xffffffffu, s, off);
                if (lane == 0) se[r] = s;
            }
            __syncthreads();
            if (tid < 32) {
                float v0 = (tid < NR) ? se[tid] : -1e30f;
                float v1 = (tid + 32 < NR) ? se[tid + 32] : -1e30f;
                float mx = fmaxf(v0, v1);
                #pragma unroll
                for (int off = 16; off; off >>= 1)
                    mx = fmaxf(mx, __shfl_xor_sync(0xffffffffu, mx, off));
                float e0 = (tid < NR) ? expf(v0 - mx) : 0.f;
                float e1 = (tid + 32 < NR) ? expf(v1 - mx) : 0.f;
                float sum = e0 + e1;
                #pragma unroll
                for (int off = 16; off; off >>= 1)
                    sum += __shfl_xor_sync(0xffffffffu, sum, off);
                float inv = 1.f / sum;
                if (tid < NR) se[tid] = e0 * inv;
                if (tid + 32 < NR) se[tid + 32] = e1 * inv;
            }
            __syncthreads();
            {
                int f0 = tid * 4;
                const float* lb = local + (size_t)b * NR * FLOC;
                float4 a = make_float4(0.f, 0.f, 0.f, 0.f);
                #pragma unroll 7
                for (int r = 0; r < NR; r++) {
                    float w = se[r];
                    float4 lv = *(const float4*)(lb + r * FLOC + f0);
                    a.x = fmaf(w, lv.x, a.x);
                    a.y = fmaf(w, lv.y, a.y);
                    a.z = fmaf(w, lv.z, a.z);
                    a.w = fmaf(w, lv.w, a.w);
                }
                split2(a.x, g_uhi[b * UD + f0 + 0], g_ulo[b * UD + f0 + 0]);
                split2(a.y, g_uhi[b * UD + f0 + 1], g_ulo[b * UD + f0 + 1]);
                split2(a.z, g_uhi[b * UD + f0 + 2], g_ulo[b * UD + f0 + 2]);
                split2(a.w, g_uhi[b * UD + f0 + 3], g_ulo[b * UD + f0 + 3]);
            }
        }
        gbar(++ep);

        // ---- Phase2: every block: A_h(t+1) then E(t) ------------------------
        {
            if (t + 1 < NT) {
                float acc[2][2][4];
                zacc<2>(acc);
                mma_res<64, 4>(g_xhi, g_xlo, XD, 512 + kcA * 128, wAh, smb, tid, acc);
                mma_store_t<2>(acc, g_P, 4 + kcA, ntA * 64, G4, tid);
            }
            float acc[2][2][4];
            zacc<2>(acc);
            mma_res<64, 3>(g_uhi, g_ulo, UD, kcE * 96, wE, smb, tid, acc);
            mma_store_t<2>(acc, g_Q, kcE, ntE * 64, NH, tid);
        }
        gbar(++ep);

        // ---- F(t): reduce 16 E-partials + tanh -> o_t -----------------------
        {
            int idx = bid * 256 + tid;
            int b = idx >> 9, n = idx & 511;
            float s = b_u[n];
            #pragma unroll
            for (int kc = 0; kc < 16; kc++)
                s += __ldcg(&g_Q[(kc * 64 + b) * NH + n]);
            s = tanhf(s);
            __nv_bfloat16 hi, lo;
            split2(s, hi, lo);
            g_xhi[b * XD + n] = hi;
            g_xlo[b * XD + n] = lo;
            int oi = (t * NB + b) * NH + n;
            g_ohi[oi] = hi;
            g_olo[oi] = lo;
        }
        gbar(++ep);

        // ---- Phase4: every block: A_o(t+1) ----------------------------------
        if (t + 1 < NT) {
            float acc[2][2][4];
            zacc<2>(acc);
            mma_res<64, 4>(g_xhi, g_xlo, XD, kcA * 128, wAo, smb, tid, acc);
            mma_store_t<2>(acc, g_P, kcA, ntA * 64, G4, tid);
        }
        gbar(++ep);
    }
}

// ---------------- general f32-input mma GEMM (attnproj / gatesy) ------------
__global__ void __launch_bounds__(256, 2)
gmma_kernel(const float* __restrict__ X, int ldx, int Mtot,
            const float* __restrict__ W, int ldw, int Nw, int K,
            const float* __restrict__ b1, const float* __restrict__ b2,
            float* __restrict__ out, int ldo)
{
    __shared__ __nv_bfloat16 sA[2][128][40];
    __shared__ __nv_bfloat16 sB[2][128][40];
    const int tid = threadIdx.x;
    const int lane = tid & 31, wid = tid >> 5;
    const int mw = wid >> 2, nw = wid & 3;
    const int gid = lane >> 2, cid = lane & 3;
    const int n0 = blockIdx.x * 128;
    const int m0 = blockIdx.y * 128;

    float acc[4][4][4];
    #pragma unroll
    for (int f = 0; f < 4; f++)
        #pragma unroll
        for (int g = 0; g < 4; g++)
            #pragma unroll
            for (int e = 0; e < 4; e++) acc[f][g][e] = 0.f;

    for (int kb = 0; kb < K; kb += 32) {
        #pragma unroll
        for (int it = 0; it < 8; it++) {
            int idx = it * 256 + tid;
            int isB = idx >> 10, rem = idx & 1023;
            int row = rem >> 3, c4 = (rem & 7) * 4;
            float4 v = make_float4(0.f, 0.f, 0.f, 0.f);
            if (!isB) {
                int gm = m0 + row;
                if (gm < Mtot) v = *(const float4*)(X + (size_t)gm * ldx + kb + c4);
            } else {
                int wr = n0 + row;
                if (wr < Nw) v = *(const float4*)(W + (size_t)wr * ldw + kb + c4);
            }
            __nv_bfloat16 h0, l0, h1, l1, h2, l2, h3, l3;
            split2(v.x, h0, l0); split2(v.y, h1, l1);
            split2(v.z, h2, l2); split2(v.w, h3, l3);
            uint2 hp = make_uint2(pbf2(h0, h1), pbf2(h2, h3));
            uint2 lp = make_uint2(pbf2(l0, l1), pbf2(l2, l3));
            if (!isB) {
                *(uint2*)(&sA[0][row][c4]) = hp;
                *(uint2*)(&sA[1][row][c4]) = lp;
            } else {
                *(uint2*)(&sB[0][row][c4]) = hp;
                *(uint2*)(&sB[1][row][c4]) = lp;
            }
        }
        __syncthreads();
        #pragma unroll
        for (int kh = 0; kh < 2; kh++) {
            int k0 = kh * 16 + 2 * cid;
            uint32_t a[4][4], bh[4][2], bl[4][2];
            #pragma unroll
            for (int f = 0; f < 4; f++) {
                const __nv_bfloat16* ap = &sA[0][mw * 64 + f * 16 + gid][k0];
                a[f][0] = *(const uint32_t*)ap;
                a[f][1] = *(const uint32_t*)(ap + 8 * 40);
                a[f][2] = *(const uint32_t*)(ap + 8);
                a[f][3] = *(const uint32_t*)(ap + 8 * 40 + 8);
            }
            #pragma unroll
            for (int g = 0; g < 4; g++) {
                const __nv_bfloat16* bp = &sB[0][nw * 32 + g * 8 + gid][k0];
                bh[g][0] = *(const uint32_t*)bp;
                bh[g][1] = *(const uint32_t*)(bp + 8);
                const __nv_bfloat16* bq = &sB[1][nw * 32 + g * 8 + gid][k0];
                bl[g][0] = *(const uint32_t*)bq;
                bl[g][1] = *(const uint32_t*)(bq + 8);
            }
            #pragma unroll
            for (int f = 0; f < 4; f++)
                #pragma unroll
                for (int g = 0; g < 4; g++) {
                    MMA_BF16(acc[f][g], a[f], bh[g]);
                    MMA_BF16(acc[f][g], a[f], bl[g]);
                }
            #pragma unroll
            for (int f = 0; f < 4; f++) {
                const __nv_bfloat16* ap = &sA[1][mw * 64 + f * 16 + gid][k0];
                a[f][0] = *(const uint32_t*)ap;
                a[f][1] = *(const uint32_t*)(ap + 8 * 40);
                a[f][2] = *(const uint32_t*)(ap + 8);
                a[f][3] = *(const uint32_t*)(ap + 8 * 40 + 8);
            }
            #pragma unroll
            for (int f = 0; f < 4; f++)
                #pragma unroll
                for (int g = 0; g < 4; g++)
                    MMA_BF16(acc[f][g], a[f], bh[g]);
        }
        __syncthreads();
    }

    float2 bias[4];
    #pragma unroll
    for (int g = 0; g < 4; g++) {
        int n = n0 + nw * 32 + g * 8 + 2 * cid;
        float2 bv = make_float2(0.f, 0.f);
        if (n < Nw) {
            if (b1) { bv.x += b1[n]; bv.y += b1[n + 1]; }
            if (b2) { bv.x += b2[n]; bv.y += b2[n + 1]; }
        }
        bias[g] = bv;
    }
    #pragma unroll
    for (int f = 0; f < 4; f++) {
        #pragma unroll
        for (int half = 0; half < 2; half++) {
            int m = m0 + mw * 64 + f * 16 + gid + half * 8;
            if (m < Mtot) {
                float* orow = out + (size_t)m * ldo;
                #pragma unroll
                for (int g = 0; g < 4; g++) {
                    int n = n0 + nw * 32 + g * 8 + 2 * cid;
                    if (n < Nw) {
                        float2 v;
                        v.x = acc[f][g][half * 2 + 0] + bias[g].x;
                        v.y = acc[f][g][half * 2 + 1] + bias[g].y;
                        *(float2*)(orow + n) = v;
                    }
                }
            }
        }
    }
}

// ---------------- vocab GEMM: cp.async double-buffered bf16 hi/lo mma -------
// smem per buffer: sA 2x128x40 (20480B) | sB 2x128x40 (20480B); 2 buffers.
__device__ __forceinline__ void vocab_issue(int tid, int m0, int n0, int kb,
                                            uint32_t sbase, int p)
{
    #pragma unroll
    for (int it = 0; it < 8; it++) {
        int idx = it * 256 + tid;
        int arr = idx >> 9, rem = idx & 511;      // arr: 0 Ahi, 1 Alo, 2 Bhi, 3 Blo
        int row = rem >> 2, c8 = (rem & 3) * 8;
        uint32_t dst = sbase + (uint32_t)(p * 40960 + arr * 10240 + row * 80 + c8 * 2);
        const __nv_bfloat16* src;
        int sz = 16;
        if (arr == 0)      src = g_ohi + (size_t)(m0 + row) * NH + kb + c8;
        else if (arr == 1) src = g_olo + (size_t)(m0 + row) * NH + kb + c8;
        else {
            int nr = n0 + row;
            const __nv_bfloat16* w = (arr == 2) ? g_Wvhi : g_Wvlo;
            src = w + (size_t)((nr < NV) ? nr : 0) * NH + kb + c8;
            if (nr >= NV) sz = 0;                 // zero-fill out-of-range rows
        }
        asm volatile("cp.async.cg.shared.global [%0], [%1], 16, %2;"
                     :: "r"(dst), "l"(src), "r"(sz));
    }
}

__global__ void __launch_bounds__(256, 2)
vocab_mma_kernel(const float* __restrict__ b_vocab, float* __restrict__ out)
{
    extern __shared__ __nv_bfloat16 vsm[];
    const int tid = threadIdx.x;
    const int lane = tid & 31, wid = tid >> 5;
    const int mw = wid >> 2, nw = wid & 3;
    const int gid = lane >> 2, cid = lane & 3;
    const int n0 = blockIdx.x * 128;
    const int m0 = blockIdx.y * 128;

    uint32_t sbase;
    asm("{ .reg .u64 t; cvta.to.shared.u64 t, %1; cvt.u32.u64 %0, t; }"
        : "=r"(sbase) : "l"(vsm));

    float acc[4][4][4];
    #pragma unroll
    for (int f = 0; f < 4; f++)
        #pragma unroll
        for (int g = 0; g < 4; g++)
            #pragma unroll
            for (int e = 0; e < 4; e++) acc[f][g][e] = 0.f;

    vocab_issue(tid, m0, n0, 0, sbase, 0);
    asm volatile("cp.async.commit_group;" ::: "memory");
    vocab_issue(tid, m0, n0, 32, sbase, 1);
    asm volatile("cp.async.commit_group;" ::: "memory");

    for (int i = 0; i < 16; i++) {
        if (i < 15) asm volatile("cp.async.wait_group 1;" ::: "memory");
        else        asm volatile("cp.async.wait_group 0;" ::: "memory");
        __syncthreads();
        const __nv_bfloat16* sAp = vsm + (i & 1) * 20480;
        const __nv_bfloat16* sBp = sAp + 10240;
        #pragma unroll
        for (int kh = 0; kh < 2; kh++) {
            int k0 = kh * 16 + 2 * cid;
            uint32_t a[4][4], bh[4][2], bl[4][2];
            #pragma unroll
            for (int f = 0; f < 4; f++) {
                const __nv_bfloat16* ap = &sAp[(mw * 64 + f * 16 + gid) * 40 + k0];
                a[f][0] = *(const uint32_t*)ap;
                a[f][1] = *(const uint32_t*)(ap + 8 * 40);
                a[f][2] = *(const uint32_t*)(ap + 8);
                a[f][3] = *(const uint32_t*)(ap + 8 * 40 + 8);
            }
            #pragma unroll
            for (int g = 0; g < 4; g++) {
                const __nv_bfloat16* bp = &sBp[(nw * 32 + g * 8 + gid) * 40 + k0];
                bh[g][0] = *(const uint32_t*)bp;
                bh[g][1] = *(const uint32_t*)(bp + 8);
                const __nv_bfloat16* bq = bp + 128 * 40;
                bl[g][0] = *(const uint32_t*)bq;
                bl[g][1] = *(const uint32_t*)(bq + 8);
            }
            #pragma unroll
            for (int f = 0; f < 4; f++)
                #pragma unroll
                for (int g = 0; g < 4; g++) {
                    MMA_BF16(acc[f][g], a[f], bh[g]);
                    MMA_BF16(acc[f][g], a[f], bl[g]);
                }
            #pragma unroll
            for (int f = 0; f < 4; f++) {
                const __nv_bfloat16* ap = &sAp[(128 + mw * 64 + f * 16 + gid) * 40 + k0];
                a[f][0] = *(const uint32_t*)ap;
                a[f][1] = *(const uint32_t*)(ap + 8 * 40);
                a[f][2] = *(const uint32_t*)(ap + 8);
                a[f][3] = *(const uint32_t*)(ap + 8 * 40 + 8);
            }
            #pragma unroll
            for (int f = 0; f < 4; f++)
                #pragma unroll
                for (int g = 0; g < 4; g++)
                    MMA_BF16(acc[f][g], a[f], bh[g]);
        }
        __syncthreads();
        if (i + 2 < 16) {
            vocab_issue(tid, m0, n0, (i + 2) * 32, sbase, i & 1);
            asm volatile("cp.async.commit_group;" ::: "memory");
        }
    }

    float2 bias[4];
    #pragma unroll
    for (int g = 0; g < 4; g++) {
        int n = n0 + nw * 32 + g * 8 + 2 * cid;
        bias[g] = (n < NV) ? *(const float2*)(b_vocab + n) : make_float2(0.f, 0.f);
    }
    #pragma unroll
    for (int f = 0; f < 4; f++) {
        int mr = m0 + mw * 64 + f * 16 + gid;
        #pragma unroll
        for (int half = 0; half < 2; half++) {
            int m = mr + half * 8;
            int b = m & 63, t = m >> 6;
            float* orow = out + ((size_t)b * NT + t) * NV;
            #pragma unroll
            for (int g = 0; g < 4; g++) {
                int n = n0 + nw * 32 + g * 8 + 2 * cid;
                if (n < NV) {
                    float2 v;
                    v.x = acc[f][g][half * 2 + 0] + bias[g].x;
                    v.y = acc[f][g][half * 2 + 1] + bias[g].y;
                    *(float2*)(orow + n) = v;
                }
            }
        }
    }
}

// ---------------------------------------------------------------------------
extern "C" void kernel_launch(void* const* d_in, const int* in_sizes, int n_in,
                              void* d_out, int out_size)
{
    const float* local   = (const float*)d_in[0];
    const float* globalf = (const float*)d_in[1];
    const float* q       = (const float*)d_in[2];
    const int*   answers = (const int*)d_in[3];
    const float* emb     = (const float*)d_in[4];
    const float* W_g2o   = (const float*)d_in[5];
    const float* b_g2o   = (const float*)d_in[6];
    const float* W_h     = (const float*)d_in[7];
    const float* W_c     = (const float*)d_in[8];
    const float* W_ih    = (const float*)d_in[9];
    const float* W_hh    = (const float*)d_in[10];
    const float* b_ih    = (const float*)d_in[11];
    const float* b_hh    = (const float*)d_in[12];
    const float* W_attn  = (const float*)d_in[13];
    const float* W_u     = (const float*)d_in[14];
    const float* b_u     = (const float*)d_in[15];
    const float* W_vocab = (const float*)d_in[16];
    const float* b_vocab = (const float*)d_in[17];
    float* out = (float*)d_out;

    cudaFuncSetAttribute(loop_kernel,      cudaFuncAttributeMaxDynamicSharedMemorySize, SMEMB);
    cudaFuncSetAttribute(vocab_mma_kernel, cudaFuncAttributeMaxDynamicSharedMemorySize, VQSMEM);

    float* d_gatesy;   cudaGetSymbolAddress((void**)&d_gatesy,   g_gatesy);
    float* d_attnproj; cudaGetSymbolAddress((void**)&d_attnproj, g_attnproj);
    float* d_yseq;     cudaGetSymbolAddress((void**)&d_yseq,     g_yseq);

    // 1) weight hi/lo splits + embedding gather
    prep_kernel<<<512, 256>>>(W_ih, W_hh, W_u, emb, answers, W_vocab);

    // 2) attn_proj = local @ W_attn^T   (M=3136, N=512, K=1024) via mma
    gmma_kernel<<<dim3(4, 25), 256>>>(
        local, FLOC, NB * NR, W_attn, FLOC, NH, FLOC,
        nullptr, nullptr, d_attnproj, NH);

    // 3) gates_y = yseq @ W_ih[:, :256]^T + b_ih + b_hh  (M=2048,N=2048,K=256)
    gmma_kernel<<<dim3(16, 16), 256>>>(
        d_yseq, NE, NT * NB, W_ih, 768, G4, NE,
        b_ih, b_hh, d_gatesy, G4);

    // 4) init states + pipelined recurrence, all tiles SM-resident, full-grid
    loop_kernel<<<NBLK, 256, SMEMB>>>(local, b_u, q, W_h, W_c,
                                      globalf, W_g2o, b_g2o);

    // 5) logits = o_all @ W_vocab^T + b_vocab  (cp.async double-buffered mma)
    vocab_mma_kernel<<<dim3((NV + 127) / 128, (NT * NB) / 128), 256, VQSMEM>>>(
        b_vocab, out);
}

// round 17
// speedup vs baseline: 1.3855x; 1.0830x over previous
#include <cuda_runtime.h>
#include <cuda_bf16.h>
#include <math.h>
#include <stdint.h>

#define NB 64
#define NT 32
#define NR 49
#define FLOC 1024
#define NQ 512
#define NE 256
#define NH 512
#define NV 10000
#define G4 2048   // 4*HID
#define XD 1024   // [o(512), h(512)]
#define UD 1536   // [a(1024), h(512)]
#define NBLK 128  // persistent kernel grid (co-resident)

typedef unsigned long long ull;

// loop smem (bytes): scratch/staging union | wAo | region2 (wAh x2 OR wE)
#define SCRATCH_B 33280
#define WAO_B     40960   // 4kb x 2(hi/lo) x 64row x 40 x 2B
#define REG2_B    81920   // blocks>=64: two wAh tiles; blocks<64: wE (61440 used)
#define SMEMB     (SCRATCH_B + WAO_B + REG2_B)

#define VQSMEM    81920   // vocab kernel: 2 x (sA 20480 + sB 20480) bytes

// ---------------- scratch (device globals; no allocation allowed) ----------
__device__ __nv_bfloat16 g_Wrechi[G4 * XD];   // recurrent weight hi/lo
__device__ __nv_bfloat16 g_Wreclo[G4 * XD];
__device__ __nv_bfloat16 g_Wuhi[NH * UD];     // W_u hi/lo
__device__ __nv_bfloat16 g_Wulo[NH * UD];
__device__ __nv_bfloat16 g_Wvhi[NV * NH];     // W_vocab hi/lo
__device__ __nv_bfloat16 g_Wvlo[NV * NH];
__device__ float g_yseq[NT * NB * NE];        // teacher-forced input embeddings
__device__ float g_gatesy[NT * NB * G4];      // y @ W_ihy^T + b_ih + b_hh
__device__ float g_attnproj[NB * NR * NH];    // local @ W_attn^T  [b][r][h]
__device__ __nv_bfloat16 g_xhi[NB * XD];      // [o,h] activations hi/lo
__device__ __nv_bfloat16 g_xlo[NB * XD];
__device__ __nv_bfloat16 g_uhi[NB * UD];      // [a,h] activations hi/lo
__device__ __nv_bfloat16 g_ulo[NB * UD];
__device__ __nv_bfloat16 g_ohi[NT * NB * NH]; // all o_t hi/lo (vocab A)
__device__ __nv_bfloat16 g_olo[NT * NB * NH];
__device__ float g_P[12 * NB * G4];           // A partials: o 0..3, h 4..7 / 8..11
__device__ float g_Q[8 * NB * NH];            // E-stage k-split partials
__device__ volatile unsigned int g_arr[NBLK];
__device__ volatile unsigned int g_rel;
__device__ unsigned int g_cntH;               // h-ready counter (monotonic)
__device__ unsigned int g_cntU;               // u-ready counter (monotonic)

// ---------------- helpers ----------------------------------------------------
__device__ __forceinline__ ull pack2(float a, float b) {
    ull r; asm("mov.b64 %0, {%1, %2};" : "=l"(r) : "f"(a), "f"(b)); return r;
}
__device__ __forceinline__ float2 unpack2(ull v) {
    float2 r; asm("mov.b64 {%0, %1}, %2;" : "=f"(r.x), "=f"(r.y) : "l"(v)); return r;
}
__device__ __forceinline__ void ffma2(ull& acc, ull a, ull b) {
    asm("fma.rn.f32x2 %0, %1, %2, %0;" : "+l"(acc) : "l"(a), "l"(b));
}
__device__ __forceinline__ void split2(float v, __nv_bfloat16& hi, __nv_bfloat16& lo) {
    hi = __float2bfloat16(v);
    lo = __float2bfloat16(v - __bfloat162float(hi));
}
__device__ __forceinline__ uint32_t pbf2(__nv_bfloat16 a, __nv_bfloat16 b) {
    __nv_bfloat162 t = __halves2bfloat162(a, b);
    return *(uint32_t*)&t;
}

#define MMA_BF16(c, a, b) \
    asm volatile("mma.sync.aligned.m16n8k16.row.col.f32.bf16.bf16.f32 " \
        "{%0,%1,%2,%3}, {%4,%5,%6,%7}, {%8,%9}, {%0,%1,%2,%3};" \
        : "+f"((c)[0]), "+f"((c)[1]), "+f"((c)[2]), "+f"((c)[3]) \
        : "r"((a)[0]), "r"((a)[1]), "r"((a)[2]), "r"((a)[3]), \
          "r"((b)[0]), "r"((b)[1]))

// ---------------- coordinator grid barrier (proven design) ------------------
__device__ __forceinline__ void gbar(unsigned int e) {
    __syncthreads();
    if (blockIdx.x == 0) {
        __threadfence();
        if (threadIdx.x == 0) g_arr[0] = e;
        if (threadIdx.x < NBLK) {
            while (g_arr[threadIdx.x] < e) { }
        }
        __threadfence();
        __syncthreads();
        if (threadIdx.x == 0) g_rel = e;
    } else {
        if (threadIdx.x == 0) {
            __threadfence();
            g_arr[blockIdx.x] = e;
            while (g_rel < e) { }
            __threadfence();
        }
        __syncthreads();
    }
}

// block-level release-arrive on a shared counter (single polled address)
__device__ __forceinline__ void cnt_arrive(unsigned int* c, int tid) {
    __syncthreads();
    if (tid == 0) { __threadfence(); atomicAdd(c, 1u); }
}
__device__ __forceinline__ void cnt_wait(unsigned int* c, unsigned int target, int tid) {
    if (tid == 0) {
        while (*(volatile unsigned int*)c < target) { }
        __threadfence();
    }
    __syncthreads();
}

// ---------------- fp32 GEMM core (prologue only): 64(m) x 64(n) -------------
__device__ __forceinline__ void gemm_core64(
    const float* __restrict__ X, int ldx,
    const float* __restrict__ W, int ldw,
    int n0, int kbase, int kSteps64,
    float* smem, int tid, ull acc[4][4])
{
    float* xs = smem;
    float* ws = smem + 64 * 65;
    int tx = tid & 15, ty = tid >> 4;
    for (int kb = 0; kb < kSteps64; kb++) {
        int kpos = kbase + kb * 64;
        #pragma unroll
        for (int it = 0; it < 4; it++) {
            int idx = it * 256 + tid;
            int row = idx >> 4, kq = (idx & 15) << 2;
            float4 v = __ldcg((const float4*)(X + row * ldx + kpos + kq));
            float* d = &xs[row * 65 + kq];
            d[0] = v.x; d[1] = v.y; d[2] = v.z; d[3] = v.w;
            float4 w = *(const float4*)(W + (size_t)(n0 + row) * ldw + kpos + kq);
            float* e = &ws[row * 65 + kq];
            e[0] = w.x; e[1] = w.y; e[2] = w.z; e[3] = w.w;
        }
        __syncthreads();
        #pragma unroll 8
        for (int k = 0; k < 64; k++) {
            ull xd[4];
            #pragma unroll
            for (int i = 0; i < 4; i++) {
                float x = xs[(ty * 4 + i) * 65 + k];
                xd[i] = pack2(x, x);
            }
            float a0 = ws[(tx * 4 + 0) * 65 + k];
            float a1 = ws[(tx * 4 + 1) * 65 + k];
            float a2 = ws[(tx * 4 + 2) * 65 + k];
            float a3 = ws[(tx * 4 + 3) * 65 + k];
            ull wA0 = pack2(a0, a1), wA1 = pack2(a2, a3);
            #pragma unroll
            for (int i = 0; i < 4; i++) {
                ffma2(acc[i][0], xd[i], wA0);
                ffma2(acc[i][1], xd[i], wA1);
            }
        }
        __syncthreads();
    }
}

__device__ __forceinline__ void store_part64(ull acc[4][4], int kc, int n0, int N, int tid)
{
    int tx = tid & 15, ty = tid >> 4;
    #pragma unroll
    for (int i = 0; i < 4; i++) {
        int m = ty * 4 + i;
        float* dst = &g_P[((kc << 6) + m) * N + n0];
        #pragma unroll
        for (int jj = 0; jj < 2; jj++)
            *(float2*)(dst + tx * 4 + jj * 2) = unpack2(acc[i][jj]);
    }
}

// ---------------- resident-weight bf16 mma core -----------------------------
template<int BN, int KSTEPS>
__device__ __forceinline__ void mma_res(
    const __nv_bfloat16* __restrict__ Ahi, const __nv_bfloat16* __restrict__ Alo,
    int lda, int kbase,
    const __nv_bfloat16* __restrict__ wRes,
    __nv_bfloat16* sA, int tid, float (&acc)[2][BN / 32][4])
{
    constexpr int NG = BN / 32;
    constexpr int ABUF = 2 * 64 * 40;
    const int lane = tid & 31, wid = tid >> 5;
    const int mw = wid >> 2, nw = wid & 3;
    const int gid = lane >> 2, cid = lane & 3;

    const int pidx0 = tid, pidx1 = 256 + tid;
    const int arr0 = pidx0 >> 8, row0 = (pidx0 & 255) >> 2, c80 = ((pidx0 & 255) & 3) * 8;
    const int arr1 = pidx1 >> 8, row1 = (pidx1 & 255) >> 2, c81 = ((pidx1 & 255) & 3) * 8;
    const __nv_bfloat16* a0base = (arr0 ? Alo : Ahi) + (size_t)row0 * lda + kbase + c80;
    const __nv_bfloat16* a1base = (arr1 ? Alo : Ahi) + (size_t)row1 * lda + kbase + c81;
    const int s0off = (arr0 * 64 + row0) * 40 + c80;
    const int s1off = (arr1 * 64 + row1) * 40 + c81;

    *(uint4*)(&sA[s0off]) = __ldcg((const uint4*)a0base);
    *(uint4*)(&sA[s1off]) = __ldcg((const uint4*)a1base);
    __syncthreads();

    for (int kb = 0; kb < KSTEPS; kb++) {
        uint4 pre0, pre1;
        bool haveNext = (kb + 1 < KSTEPS);
        if (haveNext) {
            pre0 = __ldcg((const uint4*)(a0base + (kb + 1) * 32));
            pre1 = __ldcg((const uint4*)(a1base + (kb + 1) * 32));
        }
        const __nv_bfloat16* sAc = sA + (kb & 1) * ABUF;
        const __nv_bfloat16* sB = wRes + (size_t)kb * (2 * BN * 40);
        #pragma unroll
        for (int kh = 0; kh < 2; kh++) {
            int k0 = kh * 16 + 2 * cid;
            uint32_t a[2][4], bh[NG][2], bl[NG][2];
            #pragma unroll
            for (int f = 0; f < 2; f++) {
                const __nv_bfloat16* ap = &sAc[(mw * 32 + f * 16 + gid) * 40 + k0];
                a[f][0] = *(const uint32_t*)ap;
                a[f][1] = *(const uint32_t*)(ap + 8 * 40);
                a[f][2] = *(const uint32_t*)(ap + 8);
                a[f][3] = *(const uint32_t*)(ap + 8 * 40 + 8);
            }
            #pragma unroll
            for (int g = 0; g < NG; g++) {
                const __nv_bfloat16* bp = &sB[(nw * (BN / 4) + g * 8 + gid) * 40 + k0];
                bh[g][0] = *(const uint32_t*)bp;
                bh[g][1] = *(const uint32_t*)(bp + 8);
                const __nv_bfloat16* bq = bp + (size_t)BN * 40;
                bl[g][0] = *(const uint32_t*)bq;
                bl[g][1] = *(const uint32_t*)(bq + 8);
            }
            #pragma unroll
            for (int f = 0; f < 2; f++)
                #pragma unroll
                for (int g = 0; g < NG; g++) {
                    MMA_BF16(acc[f][g], a[f], bh[g]);
                    MMA_BF16(acc[f][g], a[f], bl[g]);
                }
            #pragma unroll
            for (int f = 0; f < 2; f++) {
                const __nv_bfloat16* ap = &sAc[(64 + mw * 32 + f * 16 + gid) * 40 + k0];
                a[f][0] = *(const uint32_t*)ap;
                a[f][1] = *(const uint32_t*)(ap + 8 * 40);
                a[f][2] = *(const uint32_t*)(ap + 8);
                a[f][3] = *(const uint32_t*)(ap + 8 * 40 + 8);
            }
            #pragma unroll
            for (int f = 0; f < 2; f++)
                #pragma unroll
                for (int g = 0; g < NG; g++)
                    MMA_BF16(acc[f][g], a[f], bh[g]);
        }
        if (haveNext) {
            __nv_bfloat16* sAn = sA + ((kb + 1) & 1) * ABUF;
            *(uint4*)(&sAn[s0off]) = pre0;
            *(uint4*)(&sAn[s1off]) = pre1;
        }
        __syncthreads();
    }
}

template<int NG>
__device__ __forceinline__ void mma_store_t(float (&acc)[2][NG][4], float* buf,
                                            int slot, int n0, int N, int tid)
{
    const int lane = tid & 31, wid = tid >> 5;
    const int mw = wid >> 2, nw = wid & 3;
    const int gid = lane >> 2, cid = lane & 3;
    #pragma unroll
    for (int f = 0; f < 2; f++)
        #pragma unroll
        for (int half = 0; half < 2; half++) {
            int m = mw * 32 + f * 16 + gid + half * 8;
            float* dst = buf + ((slot << 6) + m) * N + n0 + nw * 8 * NG + 2 * cid;
            #pragma unroll
            for (int g = 0; g < NG; g++)
                *(float2*)(dst + g * 8) =
                    make_float2(acc[f][g][half * 2], acc[f][g][half * 2 + 1]);
        }
}

template<int NG>
__device__ __forceinline__ void zacc(float (&acc)[2][NG][4]) {
    #pragma unroll
    for (int f = 0; f < 2; f++)
        #pragma unroll
        for (int g = 0; g < NG; g++)
            #pragma unroll
            for (int e = 0; e < 4; e++) acc[f][g][e] = 0.f;
}

// ---------------- one-time prep: weight splits + embed gather ---------------
__global__ void prep_kernel(const float* __restrict__ W_ih,
                            const float* __restrict__ W_hh,
                            const float* __restrict__ W_u,
                            const float* __restrict__ emb,
                            const int*   __restrict__ answers,
                            const float* __restrict__ W_vocab)
{
    int stride = gridDim.x * blockDim.x;
    int tid0 = blockIdx.x * blockDim.x + threadIdx.x;
    for (int i = tid0; i < G4 * XD; i += stride) {
        int n = i >> 10, k = i & 1023;
        float w = (k < NH) ? W_ih[n * 768 + 256 + k] : W_hh[n * NH + (k - NH)];
        split2(w, g_Wrechi[i], g_Wreclo[i]);
    }
    for (int i = tid0; i < NH * UD; i += stride)
        split2(W_u[i], g_Wuhi[i], g_Wulo[i]);
    for (int i = tid0; i < NV * NH; i += stride)
        split2(W_vocab[i], g_Wvhi[i], g_Wvlo[i]);
    for (int i = tid0; i < NT * NB * NE; i += stride) {
        int m = i >> 8, e = i & 255;
        int t = m >> 6, b = m & 63;
        int tok = (t == 0) ? 1 : answers[b * NT + (t - 1)];
        g_yseq[i] = emb[tok * NE + e];
    }
}

// ---------------- persistent recurrent-loop kernel -------------------------
__global__ void __launch_bounds__(256, 1)
loop_kernel(const float* __restrict__ local,
            const float* __restrict__ b_u,
            const float* __restrict__ q,
            const float* __restrict__ W_h,
            const float* __restrict__ W_c,
            const float* __restrict__ globalf,
            const float* __restrict__ W_g2o,
            const float* __restrict__ b_g2o)
{
    extern __shared__ float smem[];
    __nv_bfloat16* smb  = (__nv_bfloat16*)smem;             // staging (bf16 view)
    __nv_bfloat16* wAo  = smb + SCRATCH_B / 2;              // resident A o-tile
    __nv_bfloat16* reg2 = smb + (SCRATCH_B + WAO_B) / 2;    // wE or wAh0/wAh1
    __nv_bfloat16* wAh0 = reg2;
    __nv_bfloat16* wAh1 = reg2 + WAO_B / 2;
    __nv_bfloat16* wE   = reg2;
    const int bid = blockIdx.x;
    const int tid = threadIdx.x;
    const int ntA = bid & 31, kcA = bid >> 5;     // A_o tile: 64n x 128k
    const int j0  = bid - 64;                     // A_h jobs (blocks >= 64)
    const int nth = j0 & 31, kch0 = j0 >> 5;      // kch0 in 0..1; job1 = kch0+2
    const int ntE = bid & 7,  kcE = bid >> 3;     // E tile (blocks < 64): 64n x 192k
    unsigned int ep = g_rel;
    unsigned int baseH = *(volatile unsigned int*)&g_cntH;
    unsigned int baseU = *(volatile unsigned int*)&g_cntU;
    float2 c_reg = make_float2(0.f, 0.f);

    // ---- Prologue W: resident weight tiles ---------------------------------
    {
        #pragma unroll
        for (int kb = 0; kb < 4; kb++) {
            #pragma unroll
            for (int it = 0; it < 2; it++) {
                int idx = it * 256 + tid;
                int arr = idx >> 8, rem = idx & 255;
                int row = rem >> 2, c8 = (rem & 3) * 8;
                const __nv_bfloat16* src = (arr ? g_Wreclo : g_Wrechi)
                    + (size_t)(ntA * 64 + row) * XD + kcA * 128 + kb * 32 + c8;
                *(uint4*)(&wAo[(kb * 2 * 64 + arr * 64 + row) * 40 + c8]) =
                    *(const uint4*)src;
            }
        }
        if (bid >= 64) {
            #pragma unroll
            for (int jj = 0; jj < 2; jj++) {
                int kch = kch0 + jj * 2;
                __nv_bfloat16* dst = jj ? wAh1 : wAh0;
                #pragma unroll
                for (int kb = 0; kb < 4; kb++) {
                    #pragma unroll
                    for (int it = 0; it < 2; it++) {
                        int idx = it * 256 + tid;
                        int arr = idx >> 8, rem = idx & 255;
                        int row = rem >> 2, c8 = (rem & 3) * 8;
                        const __nv_bfloat16* src = (arr ? g_Wreclo : g_Wrechi)
                            + (size_t)(nth * 64 + row) * XD + 512 + kch * 128 + kb * 32 + c8;
                        *(uint4*)(&dst[(kb * 2 * 64 + arr * 64 + row) * 40 + c8]) =
                            *(const uint4*)src;
                    }
                }
            }
        } else {
            #pragma unroll
            for (int kb = 0; kb < 6; kb++) {
                #pragma unroll
                for (int it = 0; it < 2; it++) {
                    int idx = it * 256 + tid;
                    int arr = idx >> 8, rem = idx & 255;
                    int row = rem >> 2, c8 = (rem & 3) * 8;
                    const __nv_bfloat16* src = (arr ? g_Wulo : g_Wuhi)
                        + (size_t)(ntE * 64 + row) * UD + kcE * 192 + kb * 32 + c8;
                    *(uint4*)(&wE[(kb * 2 * 64 + arr * 64 + row) * 40 + c8]) =
                        *(const uint4*)src;
                }
            }
        }
        __syncthreads();
    }

    // ---- Prologue P1: h0 / c0 / o0 k-split GEMMs (fp32) --------------------
    if (bid < 16) {
        int nt = bid & 7, kc = bid >> 3;
        ull acc[4][4] = {{0ULL}};
        gemm_core64(q, NQ, W_h, NQ, nt * 64, kc * 256, 4, smem, tid, acc);
        store_part64(acc, kc, nt * 64, NH, tid);
    } else if (bid < 32) {
        int nt = (bid - 16) & 7, kc = (bid - 16) >> 3;
        ull acc[4][4] = {{0ULL}};
        gemm_core64(q, NQ, W_c, NQ, nt * 64, kc * 256, 4, smem, tid, acc);
        store_part64(acc, 2 + kc, nt * 64, NH, tid);
    } else if (bid < 96) {
        int nt = (bid - 32) & 7, kc = (bid - 32) >> 3;
        ull acc[4][4] = {{0ULL}};
        gemm_core64(globalf, 2 * FLOC, W_g2o, 2 * FLOC, nt * 64, kc * 256, 4,
                    smem, tid, acc);
        store_part64(acc, 4 + kc, nt * 64, NH, tid);
    }
    gbar(++ep);

    // ---- Prologue P2: reduce into states -----------------------------------
    if (bid < NB) {
        int b = bid, j = tid * 2;
        float2 h0 = make_float2(0.f, 0.f), c0 = h0;
        float2 o0 = *(const float2*)(b_g2o + j);
        #pragma unroll
        for (int s = 0; s < 2; s++) {
            float2 v = __ldcg((const float2*)(&g_P[((s << 6) + b) * NH + j]));
            h0.x += v.x; h0.y += v.y;
        }
        #pragma unroll
        for (int s = 2; s < 4; s++) {
            float2 v = __ldcg((const float2*)(&g_P[((s << 6) + b) * NH + j]));
            c0.x += v.x; c0.y += v.y;
        }
        #pragma unroll
        for (int s = 4; s < 12; s++) {
            float2 v = __ldcg((const float2*)(&g_P[((s << 6) + b) * NH + j]));
            o0.x += v.x; o0.y += v.y;
        }
        split2(h0.x, g_xhi[b * XD + NH + j],     g_xlo[b * XD + NH + j]);
        split2(h0.y, g_xhi[b * XD + NH + j + 1], g_xlo[b * XD + NH + j + 1]);
        split2(o0.x, g_xhi[b * XD + j],          g_xlo[b * XD + j]);
        split2(o0.y, g_xhi[b * XD + j + 1],      g_xlo[b * XD + j + 1]);
        c_reg = c0;
    }
    gbar(++ep);

    // ---- Prologue P3: A_full(0): o-slot kcA (all); h-slots 4..7 (bid>=64) ---
    {
        float acc[2][2][4];
        zacc<2>(acc);
        mma_res<64, 4>(g_xhi, g_xlo, XD, kcA * 128, wAo, smb, tid, acc);
        mma_store_t<2>(acc, g_P, kcA, ntA * 64, G4, tid);
        if (bid >= 64) {
            zacc<2>(acc);
            mma_res<64, 4>(g_xhi, g_xlo, XD, 512 + kch0 * 128, wAh0, smb, tid, acc);
            mma_store_t<2>(acc, g_P, 4 + kch0, nth * 64, G4, tid);
            zacc<2>(acc);
            mma_res<64, 4>(g_xhi, g_xlo, XD, 512 + (kch0 + 2) * 128, wAh1, smb, tid, acc);
            mma_store_t<2>(acc, g_P, 4 + kch0 + 2, nth * 64, G4, tid);
        }
    }
    gbar(++ep);

    for (int t = 0; t < NT; t++) {
        const int hbt  = 4 + (t & 1) * 4;          // h-slots BD(t) reads
        const int hbt1 = 4 + ((t + 1) & 1) * 4;    // h-slots A_h(t+1) writes

        // ==== Phase 1: BD+E on blocks 0-63  ∥  A_h(t+1) on blocks 64-127 ====
        if (bid < NB) {
            float* sh = smem;
            float* se = smem + 512;
            int b = bid, j = tid * 2;
            const float* gy = &g_gatesy[(t * NB + b) * G4];
            float2 gi = *(const float2*)(gy + j);
            float2 gf = *(const float2*)(gy + NH + j);
            float2 gg = *(const float2*)(gy + 2 * NH + j);
            float2 go = *(const float2*)(gy + 3 * NH + j);
            #pragma unroll
            for (int s = 0; s < 8; s++) {
                int kc = (s < 4) ? s : (hbt + s - 4);
                const float* p = &g_P[(kc * 64 + b) * G4];
                float2 v;
                v = __ldcg((const float2*)(p + j));          gi.x += v.x; gi.y += v.y;
                v = __ldcg((const float2*)(p + NH + j));     gf.x += v.x; gf.y += v.y;
                v = __ldcg((const float2*)(p + 2 * NH + j)); gg.x += v.x; gg.y += v.y;
                v = __ldcg((const float2*)(p + 3 * NH + j)); go.x += v.x; go.y += v.y;
            }
            float2 h2;
            {
                float ig = 1.f / (1.f + expf(-gi.x));
                float fg = 1.f / (1.f + expf(-gf.x));
                float gt = tanhf(gg.x);
                float og = 1.f / (1.f + expf(-go.x));
                c_reg.x = fg * c_reg.x + ig * gt;
                h2.x = og * tanhf(c_reg.x);
            }
            {
                float ig = 1.f / (1.f + expf(-gi.y));
                float fg = 1.f / (1.f + expf(-gf.y));
                float gt = tanhf(gg.y);
                float og = 1.f / (1.f + expf(-go.y));
                c_reg.y = fg * c_reg.y + ig * gt;
                h2.y = og * tanhf(c_reg.y);
            }
            *(float2*)(sh + j) = h2;
            split2(h2.x, g_xhi[b * XD + NH + j],     g_xlo[b * XD + NH + j]);
            split2(h2.y, g_xhi[b * XD + NH + j + 1], g_xlo[b * XD + NH + j + 1]);
            split2(h2.x, g_uhi[b * UD + FLOC + j],     g_ulo[b * UD + FLOC + j]);
            split2(h2.y, g_uhi[b * UD + FLOC + j + 1], g_ulo[b * UD + FLOC + j + 1]);
            cnt_arrive(&g_cntH, tid);     // h published (includes __syncthreads)

            int warp = tid >> 5, lane = tid & 31;
            const float* pb = &g_attnproj[(size_t)b * NR * NH];
            for (int r = warp; r < NR; r += 8) {
                const float* pr = pb + r * NH;
                float s = 0.f;
                #pragma unroll
                for (int i = 0; i < 4; i++) {
                    float4 pv = *(const float4*)(pr + lane * 4 + i * 128);
                    float4 hv = *(const float4*)(sh + lane * 4 + i * 128);
                    s += pv.x * hv.x + pv.y * hv.y + pv.z * hv.z + pv.w * hv.w;
                }
                #pragma unroll
                for (int off = 16; off; off >>= 1)
                    s += __shfl_xor_sync(0xffffffffu, s, off);
                if (lane == 0) se[r] = s;
            }
            __syncthreads();
            if (tid < 32) {
                float v0 = (tid < NR) ? se[tid] : -1e30f;
                float v1 = (tid + 32 < NR) ? se[tid + 32] : -1e30f;
                float mx = fmaxf(v0, v1);
                #pragma unroll
                for (int off = 16; off; off >>= 1)
                    mx = fmaxf(mx, __shfl_xor_sync(0xffffffffu, mx, off));
                float e0 = (tid < NR) ? expf(v0 - mx) : 0.f;
                float e1 = (tid + 32 < NR) ? expf(v1 - mx) : 0.f;
                float sum = e0 + e1;
                #pragma unroll
                for (int off = 16; off; off >>= 1)
                    sum += __shfl_xor_sync(0xffffffffu, sum, off);
                float inv = 1.f / sum;
                if (tid < NR) se[tid] = e0 * inv;
                if (tid + 32 < NR) se[tid + 32] = e1 * inv;
            }
            __syncthreads();
            {
                int f0 = tid * 4;
                const float* lb = local + (size_t)b * NR * FLOC;
                float4 a = make_float4(0.f, 0.f, 0.f, 0.f);
                #pragma unroll 7
                for (int r = 0; r < NR; r++) {
                    float w = se[r];
                    float4 lv = *(const float4*)(lb + r * FLOC + f0);
                    a.x = fmaf(w, lv.x, a.x);
                    a.y = fmaf(w, lv.y, a.y);
                    a.z = fmaf(w, lv.z, a.z);
                    a.w = fmaf(w, lv.w, a.w);
                }
                split2(a.x, g_uhi[b * UD + f0 + 0], g_ulo[b * UD + f0 + 0]);
                split2(a.y, g_uhi[b * UD + f0 + 1], g_ulo[b * UD + f0 + 1]);
                split2(a.z, g_uhi[b * UD + f0 + 2], g_ulo[b * UD + f0 + 2]);
                split2(a.w, g_uhi[b * UD + f0 + 3], g_ulo[b * UD + f0 + 3]);
            }
            cnt_arrive(&g_cntU, tid);     // u published
            cnt_wait(&g_cntU, baseU + 64u * (unsigned)(t + 1), tid);

            // E(t): 8 k-splits of 192 on 64 blocks
            float acc[2][2][4];
            zacc<2>(acc);
            mma_res<64, 6>(g_uhi, g_ulo, UD, kcE * 192, wE, smb, tid, acc);
            mma_store_t<2>(acc, g_Q, kcE, ntE * 64, NH, tid);
        } else {
            if (t + 1 < NT) {
                cnt_wait(&g_cntH, baseH + 64u * (unsigned)(t + 1), tid);
                float acc[2][2][4];
                zacc<2>(acc);
                mma_res<64, 4>(g_xhi, g_xlo, XD, 512 + kch0 * 128, wAh0, smb, tid, acc);
                mma_store_t<2>(acc, g_P, hbt1 + kch0, nth * 64, G4, tid);
                zacc<2>(acc);
                mma_res<64, 4>(g_xhi, g_xlo, XD, 512 + (kch0 + 2) * 128, wAh1, smb, tid, acc);
                mma_store_t<2>(acc, g_P, hbt1 + kch0 + 2, nth * 64, G4, tid);
            }
        }
        gbar(++ep);

        // ==== Phase 2: F(t): reduce 8 E-partials + tanh -> o_t ==============
        {
            int idx = bid * 256 + tid;
            int b = idx >> 9, n = idx & 511;
            float s = b_u[n];
            #pragma unroll
            for (int kc = 0; kc < 8; kc++)
                s += __ldcg(&g_Q[(kc * 64 + b) * NH + n]);
            s = tanhf(s);
            __nv_bfloat16 hi, lo;
            split2(s, hi, lo);
            g_xhi[b * XD + n] = hi;
            g_xlo[b * XD + n] = lo;
            int oi = (t * NB + b) * NH + n;
            g_ohi[oi] = hi;
            g_olo[oi] = lo;
        }
        gbar(++ep);

        // ==== Phase 3: A_o(t+1) on all 128 blocks ===========================
        if (t + 1 < NT) {
            float acc[2][2][4];
            zacc<2>(acc);
            mma_res<64, 4>(g_xhi, g_xlo, XD, kcA * 128, wAo, smb, tid, acc);
            mma_store_t<2>(acc, g_P, kcA, ntA * 64, G4, tid);
        }
        gbar(++ep);
    }
}

// ---------------- general f32-input mma GEMM (attnproj / gatesy) ------------
__global__ void __launch_bounds__(256, 2)
gmma_kernel(const float* __restrict__ X, int ldx, int Mtot,
            const float* __restrict__ W, int ldw, int Nw, int K,
            const float* __restrict__ b1, const float* __restrict__ b2,
            float* __restrict__ out, int ldo)
{
    __shared__ __nv_bfloat16 sA[2][128][40];
    __shared__ __nv_bfloat16 sB[2][128][40];
    const int tid = threadIdx.x;
    const int lane = tid & 31, wid = tid >> 5;
    const int mw = wid >> 2, nw = wid & 3;
    const int gid = lane >> 2, cid = lane & 3;
    const int n0 = blockIdx.x * 128;
    const int m0 = blockIdx.y * 128;

    float acc[4][4][4];
    #pragma unroll
    for (int f = 0; f < 4; f++)
        #pragma unroll
        for (int g = 0; g < 4; g++)
            #pragma unroll
            for (int e = 0; e < 4; e++) acc[f][g][e] = 0.f;

    for (int kb = 0; kb < K; kb += 32) {
        #pragma unroll
        for (int it = 0; it < 8; it++) {
            int idx = it * 256 + tid;
            int isB = idx >> 10, rem = idx & 1023;
            int row = rem >> 3, c4 = (rem & 7) * 4;
            float4 v = make_float4(0.f, 0.f, 0.f, 0.f);
            if (!isB) {
                int gm = m0 + row;
                if (gm < Mtot) v = *(const float4*)(X + (size_t)gm * ldx + kb + c4);
            } else {
                int wr = n0 + row;
                if (wr < Nw) v = *(const float4*)(W + (size_t)wr * ldw + kb + c4);
            }
            __nv_bfloat16 h0, l0, h1, l1, h2, l2, h3, l3;
            split2(v.x, h0, l0); split2(v.y, h1, l1);
            split2(v.z, h2, l2); split2(v.w, h3, l3);
            uint2 hp = make_uint2(pbf2(h0, h1), pbf2(h2, h3));
            uint2 lp = make_uint2(pbf2(l0, l1), pbf2(l2, l3));
            if (!isB) {
                *(uint2*)(&sA[0][row][c4]) = hp;
                *(uint2*)(&sA[1][row][c4]) = lp;
            } else {
                *(uint2*)(&sB[0][row][c4]) = hp;
                *(uint2*)(&sB[1][row][c4]) = lp;
            }
        }
        __syncthreads();
        #pragma unroll
        for (int kh = 0; kh < 2; kh++) {
            int k0 = kh * 16 + 2 * cid;
            uint32_t a[4][4], bh[4][2], bl[4][2];
            #pragma unroll
            for (int f = 0; f < 4; f++) {
                const __nv_bfloat16* ap = &sA[0][mw * 64 + f * 16 + gid][k0];
                a[f][0] = *(const uint32_t*)ap;
                a[f][1] = *(const uint32_t*)(ap + 8 * 40);
                a[f][2] = *(const uint32_t*)(ap + 8);
                a[f][3] = *(const uint32_t*)(ap + 8 * 40 + 8);
            }
            #pragma unroll
            for (int g = 0; g < 4; g++) {
                const __nv_bfloat16* bp = &sB[0][nw * 32 + g * 8 + gid][k0];
                bh[g][0] = *(const uint32_t*)bp;
                bh[g][1] = *(const uint32_t*)(bp + 8);
                const __nv_bfloat16* bq = &sB[1][nw * 32 + g * 8 + gid][k0];
                bl[g][0] = *(const uint32_t*)bq;
                bl[g][1] = *(const uint32_t*)(bq + 8);
            }
            #pragma unroll
            for (int f = 0; f < 4; f++)
                #pragma unroll
                for (int g = 0; g < 4; g++) {
                    MMA_BF16(acc[f][g], a[f], bh[g]);
                    MMA_BF16(acc[f][g], a[f], bl[g]);
                }
            #pragma unroll
            for (int f = 0; f < 4; f++) {
                const __nv_bfloat16* ap = &sA[1][mw * 64 + f * 16 + gid][k0];
                a[f][0] = *(const uint32_t*)ap;
                a[f][1] = *(const uint32_t*)(ap + 8 * 40);
                a[f][2] = *(const uint32_t*)(ap + 8);
                a[f][3] = *(const uint32_t*)(ap + 8 * 40 + 8);
            }
            #pragma unroll
            for (int f = 0; f < 4; f++)
                #pragma unroll
                for (int g = 0; g < 4; g++)
                    MMA_BF16(acc[f][g], a[f], bh[g]);
        }
        __syncthreads();
    }

    float2 bias[4];
    #pragma unroll
    for (int g = 0; g < 4; g++) {
        int n = n0 + nw * 32 + g * 8 + 2 * cid;
        float2 bv = make_float2(0.f, 0.f);
        if (n < Nw) {
            if (b1) { bv.x += b1[n]; bv.y += b1[n + 1]; }
            if (b2) { bv.x += b2[n]; bv.y += b2[n + 1]; }
        }
        bias[g] = bv;
    }
    #pragma unroll
    for (int f = 0; f < 4; f++) {
        #pragma unroll
        for (int half = 0; half < 2; half++) {
            int m = m0 + mw * 64 + f * 16 + gid + half * 8;
            if (m < Mtot) {
                float* orow = out + (size_t)m * ldo;
                #pragma unroll
                for (int g = 0; g < 4; g++) {
                    int n = n0 + nw * 32 + g * 8 + 2 * cid;
                    if (n < Nw) {
                        float2 v;
                        v.x = acc[f][g][half * 2 + 0] + bias[g].x;
                        v.y = acc[f][g][half * 2 + 1] + bias[g].y;
                        *(float2*)(orow + n) = v;
                    }
                }
            }
        }
    }
}

// ---------------- vocab GEMM: cp.async double-buffered bf16 hi/lo mma -------
__device__ __forceinline__ void vocab_issue(int tid, int m0, int n0, int kb,
                                            uint32_t sbase, int p)
{
    #pragma unroll
    for (int it = 0; it < 8; it++) {
        int idx = it * 256 + tid;
        int arr = idx >> 9, rem = idx & 511;      // 0 Ahi, 1 Alo, 2 Bhi, 3 Blo
        int row = rem >> 2, c8 = (rem & 3) * 8;
        uint32_t dst = sbase + (uint32_t)(p * 40960 + arr * 10240 + row * 80 + c8 * 2);
        const __nv_bfloat16* src;
        int sz = 16;
        if (arr == 0)      src = g_ohi + (size_t)(m0 + row) * NH + kb + c8;
        else if (arr == 1) src = g_olo + (size_t)(m0 + row) * NH + kb + c8;
        else {
            int nr = n0 + row;
            const __nv_bfloat16* w = (arr == 2) ? g_Wvhi : g_Wvlo;
            src = w + (size_t)((nr < NV) ? nr : 0) * NH + kb + c8;
            if (nr >= NV) sz = 0;
        }
        asm volatile("cp.async.cg.shared.global [%0], [%1], 16, %2;"
                     :: "r"(dst), "l"(src), "r"(sz));
    }
}

__global__ void __launch_bounds__(256, 2)
vocab_mma_kernel(const float* __restrict__ b_vocab, float* __restrict__ out)
{
    extern __shared__ __nv_bfloat16 vsm[];
    const int tid = threadIdx.x;
    const int lane = tid & 31, wid = tid >> 5;
    const int mw = wid >> 2, nw = wid & 3;
    const int gid = lane >> 2, cid = lane & 3;
    const int n0 = blockIdx.x * 128;
    const int m0 = blockIdx.y * 128;

    uint32_t sbase;
    asm("{ .reg .u64 t; cvta.to.shared.u64 t, %1; cvt.u32.u64 %0, t; }"
        : "=r"(sbase) : "l"(vsm));

    float acc[4][4][4];
    #pragma unroll
    for (int f = 0; f < 4; f++)
        #pragma unroll
        for (int g = 0; g < 4; g++)
            #pragma unroll
            for (int e = 0; e < 4; e++) acc[f][g][e] = 0.f;

    vocab_issue(tid, m0, n0, 0, sbase, 0);
    asm volatile("cp.async.commit_group;" ::: "memory");
    vocab_issue(tid, m0, n0, 32, sbase, 1);
    asm volatile("cp.async.commit_group;" ::: "memory");

    for (int i = 0; i < 16; i++) {
        if (i < 15) asm volatile("cp.async.wait_group 1;" ::: "memory");
        else        asm volatile("cp.async.wait_group 0;" ::: "memory");
        __syncthreads();
        const __nv_bfloat16* sAp = vsm + (i & 1) * 20480;
        const __nv_bfloat16* sBp = sAp + 10240;
        #pragma unroll
        for (int kh = 0; kh < 2; kh++) {
            int k0 = kh * 16 + 2 * cid;
            uint32_t a[4][4], bh[4][2], bl[4][2];
            #pragma unroll
            for (int f = 0; f < 4; f++) {
                const __nv_bfloat16* ap = &sAp[(mw * 64 + f * 16 + gid) * 40 + k0];
                a[f][0] = *(const uint32_t*)ap;
                a[f][1] = *(const uint32_t*)(ap + 8 * 40);
                a[f][2] = *(const uint32_t*)(ap + 8);
                a[f][3] = *(const uint32_t*)(ap + 8 * 40 + 8);
            }
            #pragma unroll
            for (int g = 0; g < 4; g++) {
                const __nv_bfloat16* bp = &sBp[(nw * 32 + g * 8 + gid) * 40 + k0];
                bh[g][0] = *(const uint32_t*)bp;
                bh[g][1] = *(const uint32_t*)(bp + 8);
                const __nv_bfloat16* bq = bp + 128 * 40;
                bl[g][0] = *(const uint32_t*)bq;
                bl[g][1] = *(const uint32_t*)(bq + 8);
            }
            #pragma unroll
            for (int f = 0; f < 4; f++)
                #pragma unroll
                for (int g = 0; g < 4; g++) {
                    MMA_BF16(acc[f][g], a[f], bh[g]);
                    MMA_BF16(acc[f][g], a[f], bl[g]);
                }
            #pragma unroll
            for (int f = 0; f < 4; f++) {
                const __nv_bfloat16* ap = &sAp[(128 + mw * 64 + f * 16 + gid) * 40 + k0];
                a[f][0] = *(const uint32_t*)ap;
                a[f][1] = *(const uint32_t*)(ap + 8 * 40);
                a[f][2] = *(const uint32_t*)(ap + 8);
                a[f][3] = *(const uint32_t*)(ap + 8 * 40 + 8);
            }
            #pragma unroll
            for (int f = 0; f < 4; f++)
                #pragma unroll
                for (int g = 0; g < 4; g++)
                    MMA_BF16(acc[f][g], a[f], bh[g]);
        }
        __syncthreads();
        if (i + 2 < 16) {
            vocab_issue(tid, m0, n0, (i + 2) * 32, sbase, i & 1);
            asm volatile("cp.async.commit_group;" ::: "memory");
        }
    }

    float2 bias[4];
    #pragma unroll
    for (int g = 0; g < 4; g++) {
        int n = n0 + nw * 32 + g * 8 + 2 * cid;
        bias[g] = (n < NV) ? *(const float2*)(b_vocab + n) : make_float2(0.f, 0.f);
    }
    #pragma unroll
    for (int f = 0; f < 4; f++) {
        int mr = m0 + mw * 64 + f * 16 + gid;
        #pragma unroll
        for (int half = 0; half < 2; half++) {
            int m = mr + half * 8;
            int b = m & 63, t = m >> 6;
            float* orow = out + ((size_t)b * NT + t) * NV;
            #pragma unroll
            for (int g = 0; g < 4; g++) {
                int n = n0 + nw * 32 + g * 8 + 2 * cid;
                if (n < NV) {
                    float2 v;
                    v.x = acc[f][g][half * 2 + 0] + bias[g].x;
                    v.y = acc[f][g][half * 2 + 1] + bias[g].y;
                    *(float2*)(orow + n) = v;
                }
            }
        }
    }
}

// ---------------------------------------------------------------------------
extern "C" void kernel_launch(void* const* d_in, const int* in_sizes, int n_in,
                              void* d_out, int out_size)
{
    const float* local   = (const float*)d_in[0];
    const float* globalf = (const float*)d_in[1];
    const float* q       = (const float*)d_in[2];
    const int*   answers = (const int*)d_in[3];
    const float* emb     = (const float*)d_in[4];
    const float* W_g2o   = (const float*)d_in[5];
    const float* b_g2o   = (const float*)d_in[6];
    const float* W_h     = (const float*)d_in[7];
    const float* W_c     = (const float*)d_in[8];
    const float* W_ih    = (const float*)d_in[9];
    const float* W_hh    = (const float*)d_in[10];
    const float* b_ih    = (const float*)d_in[11];
    const float* b_hh    = (const float*)d_in[12];
    const float* W_attn  = (const float*)d_in[13];
    const float* W_u     = (const float*)d_in[14];
    const float* b_u     = (const float*)d_in[15];
    const float* W_vocab = (const float*)d_in[16];
    const float* b_vocab = (const float*)d_in[17];
    float* out = (float*)d_out;

    cudaFuncSetAttribute(loop_kernel,      cudaFuncAttributeMaxDynamicSharedMemorySize, SMEMB);
    cudaFuncSetAttribute(vocab_mma_kernel, cudaFuncAttributeMaxDynamicSharedMemorySize, VQSMEM);

    float* d_gatesy;   cudaGetSymbolAddress((void**)&d_gatesy,   g_gatesy);
    float* d_attnproj; cudaGetSymbolAddress((void**)&d_attnproj, g_attnproj);
    float* d_yseq;     cudaGetSymbolAddress((void**)&d_yseq,     g_yseq);

    // 1) weight hi/lo splits + embedding gather
    prep_kernel<<<512, 256>>>(W_ih, W_hh, W_u, emb, answers, W_vocab);

    // 2) attn_proj = local @ W_attn^T   (M=3136, N=512, K=1024) via mma
    gmma_kernel<<<dim3(4, 25), 256>>>(
        local, FLOC, NB * NR, W_attn, FLOC, NH, FLOC,
        nullptr, nullptr, d_attnproj, NH);

    // 3) gates_y = yseq @ W_ih[:, :256]^T + b_ih + b_hh  (M=2048,N=2048,K=256)
    gmma_kernel<<<dim3(16, 16), 256>>>(
        d_yseq, NE, NT * NB, W_ih, 768, G4, NE,
        b_ih, b_hh, d_gatesy, G4);

    // 4) recurrence: producer/consumer overlapped phase-1, 3 global barriers
    loop_kernel<<<NBLK, 256, SMEMB>>>(local, b_u, q, W_h, W_c,
                                      globalf, W_g2o, b_g2o);

    // 5) logits = o_all @ W_vocab^T + b_vocab  (cp.async double-buffered mma)
    vocab_mma_kernel<<<dim3((NV + 127) / 128, (NT * NB) / 128), 256, VQSMEM>>>(
        b_vocab, out);
}